// round 14
// baseline (speedup 1.0000x reference)
#include <cuda_runtime.h>
#include <cuda_fp16.h>
#include <mma.h>
#include <math.h>
#include <stdint.h>

using namespace nvcuda;

#define DD 300
#define NCOLS 1800
#define KK2 320
#define MAXN 50000
#define MAXE 250000
#define MPAD 50048
#define STAGES 3
#define KT 32
#define NT (KK2 / KT)
#define SFST 608            // d_Sf (fp16): Q[0..300), Cd[304..604)
#define SHST 960            // d_Sh (fp16): K[0..300), V[320..620), Cs[640..940)

__device__ __half d_Ah[(size_t)MPAD * KK2];
__device__ __half d_WhT[(size_t)1920 * KK2];
__device__ __half d_Sf[(size_t)MPAD * SFST];
__device__ __half d_Sh[(size_t)MPAD * SHST];
__device__ float  d_NLi[3 * DD];
__device__ float  d_NLj[3 * DD];
__device__ float  d_W2f[2 * DD];
__device__ float  d_c0[DD];
__device__ float  d_T8[8 * DD];
__device__ float  d_G8[8 * DD];
__device__ int  d_deg[MAXN];
__device__ int  d_rowptr[MAXN + 1];
__device__ int  d_cursor[MAXN];
__device__ int  d_blksum[256];
__device__ int2 d_edges[MAXE];

__device__ __forceinline__ float fast_tanh(float x) {
    float r;
    asm("tanh.approx.f32 %0, %1;" : "=f"(r) : "f"(x));
    return r;
}

// ---------------- fold1b ----------------
__global__ void __launch_bounds__(128) fold1b_kernel(
        const float* __restrict__ Wn, const float* __restrict__ Wxy,
        const float* __restrict__ Wloc, const float* __restrict__ Wfus,
        const float* __restrict__ vocab, const float* __restrict__ bxy,
        const float* __restrict__ bn, const float* __restrict__ bobj,
        const float* __restrict__ bloc, const float* __restrict__ bfus) {
    int c = blockIdx.x;
    int t = threadIdx.x;
    float pt[16];
    #pragma unroll
    for (int j = 0; j < 16; j++) pt[j] = 0.0f;

    for (int k = t; k < DD; k += 128) {
        float wl0 = Wloc[k * DD + c];
        float wl1 = Wloc[(DD + k) * DD + c];
        float wl2 = Wloc[(2 * DD + k) * DD + c];
        float wn0 = Wn[k], wn1 = Wn[DD + k], wn2 = Wn[2 * DD + k];
        pt[0] = fmaf(wn0, wl1, pt[0]); pt[1] = fmaf(wn1, wl1, pt[1]); pt[2] = fmaf(wn2, wl1, pt[2]);
        pt[3] = fmaf(wn0, wl2, pt[3]); pt[4] = fmaf(wn1, wl2, pt[4]); pt[5] = fmaf(wn2, wl2, pt[5]);
        pt[6] = fmaf(Wxy[k], wl0, pt[6]); pt[7] = fmaf(Wxy[DD + k], wl0, pt[7]);
        pt[8] = fmaf(bxy[k], wl0, pt[8]);
        pt[8] = fmaf(bn[k], wl1 + wl2, pt[8]);
        float wf0 = Wfus[k * DD + c];
        float wf1 = Wfus[(DD + k) * DD + c];
        pt[9]  = fmaf(vocab[2 * DD + k], wf1, pt[9]);
        pt[10] = fmaf(vocab[3 * DD + k], wf1, pt[10]);
        pt[11] = fmaf(vocab[4 * DD + k], wf1, pt[11]);
        pt[12] = fmaf(vocab[5 * DD + k], wf1, pt[12]);
        pt[13] = fmaf(vocab[6 * DD + k], wf1, pt[13]);
        pt[14] = fmaf(vocab[k], wf0, pt[14]);
        pt[15] = fmaf(vocab[DD + k], wf0, pt[15]);
    }

    __shared__ float sd[16][128];
    #pragma unroll
    for (int j = 0; j < 16; j++) sd[j][t] = pt[j];
    __syncthreads();
    #pragma unroll
    for (int off = 64; off; off >>= 1) {
        if (t < off) {
            #pragma unroll
            for (int j = 0; j < 16; j++) sd[j][t] += sd[j][t + off];
        }
        __syncthreads();
    }
    if (t == 0) {
        d_NLi[0 * DD + c] = sd[0][0]; d_NLi[1 * DD + c] = sd[1][0]; d_NLi[2 * DD + c] = sd[2][0];
        d_NLj[0 * DD + c] = sd[3][0]; d_NLj[1 * DD + c] = sd[4][0]; d_NLj[2 * DD + c] = sd[5][0];
        d_W2f[c] = sd[6][0]; d_W2f[DD + c] = sd[7][0];
        d_c0[c] = sd[8][0] + bobj[c] + bloc[c];
        d_T8[0 * DD + c] = sd[9][0];  d_T8[1 * DD + c] = sd[10][0];
        d_T8[2 * DD + c] = sd[11][0]; d_T8[3 * DD + c] = sd[12][0];
        d_T8[4 * DD + c] = sd[13][0]; d_T8[5 * DD + c] = sd[14][0];
        d_T8[6 * DD + c] = sd[15][0]; d_T8[7 * DD + c] = bfus[c];
    }
}

// ---------------- fold2b ----------------
__global__ void __launch_bounds__(64) fold2b_kernel(const float* __restrict__ We) {
    int c = blockIdx.x;
    int t = threadIdx.x;
    float g[8];
    #pragma unroll
    for (int j = 0; j < 8; j++) g[j] = 0.0f;
    for (int k = t; k < DD; k += 64) {
        float w = We[k * DD + c];
        #pragma unroll
        for (int j = 0; j < 8; j++) g[j] = fmaf(d_T8[j * DD + k], w, g[j]);
    }
    __shared__ float sd[8][64];
    #pragma unroll
    for (int j = 0; j < 8; j++) sd[j][t] = g[j];
    __syncthreads();
    #pragma unroll
    for (int off = 32; off; off >>= 1) {
        if (t < off) {
            #pragma unroll
            for (int j = 0; j < 8; j++) sd[j][t] += sd[j][t + off];
        }
        __syncthreads();
    }
    if (t == 0) {
        #pragma unroll
        for (int j = 0; j < 8; j++) d_G8[j * DD + c] = sd[j][0];
    }
}

// ---------------- build A ----------------
__global__ void buildA_kernel(const float* __restrict__ x, const float* __restrict__ nrm, int Nn) {
    int idx = blockIdx.x * blockDim.x + threadIdx.x;
    if (idx >= Nn * 304) return;
    int n = idx / 304, k = idx - n * 304;
    float v;
    if (k < DD) v = x[n * DD + k];
    else if (k < DD + 3) v = nrm[n * 3 + (k - DD)];
    else v = 1.0f;
    d_Ah[(size_t)n * KK2 + k] = __float2half_rn(v);
}

// ---------------- build WhT ----------------
__global__ void buildW_kernel(const float* __restrict__ Wq, const float* __restrict__ Wk,
                              const float* __restrict__ Wv, const float* __restrict__ Wskip,
                              const float* __restrict__ Wobj, const float* __restrict__ bq,
                              const float* __restrict__ bk, const float* __restrict__ bv,
                              const float* __restrict__ bskip) {
    int idx = blockIdx.x * blockDim.x + threadIdx.x;
    if (idx >= NCOLS * 304) return;
    int c = idx / 304, k = idx - c * 304;
    int b = c / DD, cc = c - b * DD;
    float v = 0.0f;
    if (k < DD) {
        if (b == 0) v = Wq[k * DD + cc];
        else if (b == 1) v = Wk[k * DD + cc];
        else if (b == 2) v = Wv[k * DD + cc];
        else if (b == 3) v = Wskip[k * DD + cc];
        else if (b == 4) v = Wobj[k * DD + cc] - Wobj[(DD + k) * DD + cc];
        else v = Wobj[(DD + k) * DD + cc];
    } else if (k < DD + 3) {
        int r = k - DD;
        if (b == 4) v = d_NLi[r * DD + cc];
        else if (b == 5) v = d_NLj[r * DD + cc];
    } else {
        if (b == 0) v = bq[cc];
        else if (b == 1) v = bk[cc];
        else if (b == 2) v = bv[cc];
        else if (b == 3) v = bskip[cc];
        else if (b == 4) v = d_c0[cc];
    }
    d_WhT[(size_t)c * KK2 + k] = __float2half_rn(v);
}

// ---------------- node GEMM: 3-stage, 3 CTAs/SM, two-pass epilogue ----------------
__global__ void __launch_bounds__(256, 3) gemm_fp16_kernel(float* __restrict__ out, int Nn) {
    extern __shared__ __half sm[];
    __half (*As)[128][40] = (__half (*)[128][40])sm;
    __half (*Bs)[128][40] = (__half (*)[128][40])(sm + STAGES * 128 * 40);
    float (*stage)[132] = (float (*)[132])sm;   // 64 x 132 epilogue reuse

    int tid = threadIdx.x;
    int wid = tid >> 5;
    int wm = wid >> 2;
    int wn = wid & 3;
    int row0 = blockIdx.y * 128, col0 = blockIdx.x * 128;

    wmma::fragment<wmma::accumulator, 16, 16, 16, float> acc[4][2];
    #pragma unroll
    for (int i = 0; i < 4; i++)
        #pragma unroll
        for (int j = 0; j < 2; j++) wmma::fill_fragment(acc[i][j], 0.0f);

    auto loadStage = [&](int st, int kt) {
        #pragma unroll
        for (int u = 0; u < 2; u++) {
            int idx = tid + 256 * u;
            int row = idx >> 2, seg = idx & 3;
            const __half* ga = &d_Ah[(size_t)(row0 + row) * KK2 + kt + seg * 8];
            uint32_t da = (uint32_t)__cvta_generic_to_shared(&As[st][row][seg * 8]);
            asm volatile("cp.async.cg.shared.global [%0], [%1], 16;" :: "r"(da), "l"(ga));
            const __half* gb = &d_WhT[(size_t)(col0 + row) * KK2 + kt + seg * 8];
            uint32_t db = (uint32_t)__cvta_generic_to_shared(&Bs[st][row][seg * 8]);
            asm volatile("cp.async.cg.shared.global [%0], [%1], 16;" :: "r"(db), "l"(gb));
        }
    };

    #pragma unroll
    for (int i = 0; i < STAGES - 1; i++) {
        loadStage(i, i * KT);
        asm volatile("cp.async.commit_group;");
    }

    int stq = 0;
    for (int s = 0; s < NT; s++) {
        asm volatile("cp.async.wait_group %0;" :: "n"(STAGES - 2));
        __syncthreads();
        int ld = s + STAGES - 1;
        if (ld < NT) {
            int st = (stq + STAGES - 1) % STAGES;
            loadStage(st, ld * KT);
        }
        asm volatile("cp.async.commit_group;");

        int st = stq;
        #pragma unroll
        for (int ks = 0; ks < 2; ks++) {
            int k0 = ks * 16;
            wmma::fragment<wmma::matrix_b, 16, 16, 16, __half, wmma::col_major> bf[2];
            #pragma unroll
            for (int j = 0; j < 2; j++)
                wmma::load_matrix_sync(bf[j], &Bs[st][wn * 32 + j * 16][k0], 40);
            #pragma unroll
            for (int i = 0; i < 4; i++) {
                wmma::fragment<wmma::matrix_a, 16, 16, 16, __half, wmma::row_major> af;
                wmma::load_matrix_sync(af, &As[st][wm * 64 + i * 16][k0], 40);
                #pragma unroll
                for (int j = 0; j < 2; j++)
                    wmma::mma_sync(acc[i][j], af, bf[j], acc[i][j]);
            }
        }
        stq++;
        if (stq == STAGES) stq = 0;
    }

    asm volatile("cp.async.wait_group 0;");
    __syncthreads();

    // two-pass epilogue: pass h stages rows [h*64, h*64+64)
    #pragma unroll
    for (int hp = 0; hp < 2; hp++) {
        if (wm == hp) {
            #pragma unroll
            for (int i = 0; i < 4; i++)
                #pragma unroll
                for (int j = 0; j < 2; j++)
                    wmma::store_matrix_sync(&stage[i * 16][wn * 32 + j * 16],
                                            acc[i][j], 132, wmma::mem_row_major);
        }
        __syncthreads();
        #pragma unroll
        for (int it = 0; it < 8; it++) {
            int idx = tid + it * 256;        // 0..2047 (64 rows x 32 groups)
            int r = idx >> 5;
            int c4 = (idx & 31) * 4;
            int gc = col0 + c4;
            if (gc < NCOLS) {
                int n = row0 + hp * 64 + r;
                float4 v = *(float4*)&stage[r][c4];
                int b = gc / DD;
                int cc = gc - b * DD;
                if (b == 3) {
                    if (n < Nn) *(float4*)&out[(size_t)n * DD + cc] = v;
                } else {
                    __half2 h0 = __floats2half2_rn(v.x, v.y);
                    __half2 h1 = __floats2half2_rn(v.z, v.w);
                    uint2 u = make_uint2(*(uint32_t*)&h0, *(uint32_t*)&h1);
                    if (b == 0) {
                        *(uint2*)&d_Sf[(size_t)n * SFST + cc] = u;
                    } else if (b == 4) {
                        *(uint2*)&d_Sf[(size_t)n * SFST + 304 + cc] = u;
                    } else {
                        int off = (b == 1) ? 0 : (b == 2 ? 320 : 640);
                        *(uint2*)&d_Sh[(size_t)n * SHST + off + cc] = u;
                    }
                }
            }
        }
        __syncthreads();
    }
}

// ---------------- CSR build ----------------
__global__ void zerodeg_kernel(int Nn) {
    int i = blockIdx.x * blockDim.x + threadIdx.x;
    if (i < Nn) d_deg[i] = 0;
}
__global__ void hist_kernel(const int* __restrict__ EI, int Ee) {
    int e = blockIdx.x * blockDim.x + threadIdx.x;
    if (e < Ee) atomicAdd(&d_deg[EI[Ee + e]], 1);
}
__global__ void scan1_kernel(int Nn) {
    __shared__ int sdata[256];
    int t = threadIdx.x;
    int i = blockIdx.x * 256 + t;
    int v = (i < Nn) ? d_deg[i] : 0;
    sdata[t] = v;
    __syncthreads();
    #pragma unroll
    for (int off = 1; off < 256; off <<= 1) {
        int x = (t >= off) ? sdata[t - off] : 0;
        __syncthreads();
        sdata[t] += x;
        __syncthreads();
    }
    if (i < Nn) d_rowptr[i] = sdata[t] - v;
    if (t == 255) d_blksum[blockIdx.x] = sdata[255];
}
__global__ void scan2_kernel(int NB) {
    __shared__ int sdata[256];
    int t = threadIdx.x;
    int v = (t < NB) ? d_blksum[t] : 0;
    sdata[t] = v;
    __syncthreads();
    #pragma unroll
    for (int off = 1; off < 256; off <<= 1) {
        int x = (t >= off) ? sdata[t - off] : 0;
        __syncthreads();
        sdata[t] += x;
        __syncthreads();
    }
    if (t < NB) d_blksum[t] = sdata[t] - v;
}
__global__ void scan3_kernel(int Nn) {
    int i = blockIdx.x * blockDim.x + threadIdx.x;
    if (i >= Nn) return;
    int val = d_rowptr[i] + d_blksum[i >> 8];
    d_rowptr[i] = val;
    d_cursor[i] = val;
    if (i == Nn - 1) d_rowptr[Nn] = val + d_deg[i];
}
__global__ void scatter_kernel(const int* __restrict__ EI, int Ee) {
    int e = blockIdx.x * blockDim.x + threadIdx.x;
    if (e >= Ee) return;
    int dst = EI[Ee + e];
    int pos = atomicAdd(&d_cursor[dst], 1);
    d_edges[pos] = make_int2(EI[e], e);
}

// ---------------- edgeF v5: no max-subtraction ----------------
__global__ void __launch_bounds__(128, 5) edgeF_kernel(const float* __restrict__ EA,
                                                       const float* __restrict__ Wcls,
                                                       const float* __restrict__ bcls,
                                                       float* __restrict__ out, int Nn) {
    __shared__ float sWc[5 * DD];
    __shared__ float sG[8 * DD];
    __shared__ float2 sW2[DD];
    __shared__ float sBcls[5];
    for (int i = threadIdx.x; i < 5 * DD; i += 128) {
        int k = i / DD, c = i - k * DD;
        sWc[i] = Wcls[c * 5 + k];
    }
    for (int i = threadIdx.x; i < 8 * DD; i += 128) sG[i] = d_G8[i];
    for (int i = threadIdx.x; i < DD; i += 128)
        sW2[i] = make_float2(d_W2f[i], d_W2f[DD + i]);
    if (threadIdx.x < 5) sBcls[threadIdx.x] = bcls[threadIdx.x];
    __syncthreads();

    const uint32_t FULL = 0xffffffffu;
    int lane = threadIdx.x & 31;
    int warp = threadIdx.x >> 5;
    int oh = lane >> 3, oj = lane & 7;
    const float sc = 0.115470053837925152f;  // 1/sqrt(75)

    for (int n = blockIdx.x * 4 + warp; n < Nn; n += gridDim.x * 4) {
        int beg = d_rowptr[n], end = d_rowptr[n + 1];
        const __half* rowQ = d_Sf + (size_t)n * SFST;

        float QG = 0.0f;
        {
            const __half* qb = rowQ + oh * 75;
            const float* gb = sG + oj * DD + oh * 75;
            #pragma unroll 5
            for (int c = 0; c < 75; c++)
                QG = fmaf(__half2float(__ldg(&qb[c])), gb[c], QG);
        }

        float2 q2[5], cd2[5], av[5];
        #pragma unroll
        for (int s = 0; s < 5; s++) {
            int col = 2 * lane + 64 * s;
            bool ok = col < DD;
            if (ok) {
                q2[s]  = __half22float2(*(const __half2*)(rowQ + col));
                cd2[s] = __half22float2(*(const __half2*)(rowQ + 304 + col));
            } else {
                q2[s] = make_float2(0, 0);
                cd2[s] = make_float2(0, 0);
            }
            av[s] = make_float2(0, 0);
        }
        float Tacc = 0.0f;

        for (int p = beg; p < end; p++) {
            int2 se = __ldg(&d_edges[p]);
            const __half* rowS = d_Sh + (size_t)se.x * SHST;
            float4 ea = __ldg((const float4*)&EA[4 * se.y]);

            uint32_t kh[5], vh[5], ch[5];
            #pragma unroll
            for (int s = 0; s < 5; s++) {
                int col = 2 * lane + 64 * s;
                bool ok = col < DD;
                kh[s] = ok ? __ldg((const uint32_t*)(rowS + col)) : 0u;
                vh[s] = ok ? __ldg((const uint32_t*)(rowS + 320 + col)) : 0u;
                ch[s] = ok ? __ldg((const uint32_t*)(rowS + 640 + col)) : 0u;
            }

            float vf0[5], vf1[5];
            float l0 = 0, l1 = 0, l2 = 0, l3 = 0, l4 = 0;
            float a0 = 0, a1 = 0, a2 = 0, a3 = 0;
            #pragma unroll
            for (int s = 0; s < 5; s++) {
                int col = 2 * lane + 64 * s;
                float2 kf = __half22float2(*(__half2*)&kh[s]);
                float2 vf = __half22float2(*(__half2*)&vh[s]);
                float2 cf = __half22float2(*(__half2*)&ch[s]);
                vf0[s] = vf.x; vf1[s] = vf.y;
                if (col < DD) {
                    #pragma unroll
                    for (int i = 0; i < 2; i++) {
                        int c = col + i;
                        float2 w2 = sW2[c];
                        float cdv = i ? cd2[s].y : cd2[s].x;
                        float csv = i ? cf.y : cf.x;
                        float h = fast_tanh(cdv + csv + ea.z * w2.x + ea.w * w2.y);
                        l0 = fmaf(h, sWc[c], l0);
                        l1 = fmaf(h, sWc[DD + c], l1);
                        l2 = fmaf(h, sWc[2 * DD + c], l2);
                        l3 = fmaf(h, sWc[3 * DD + c], l3);
                        l4 = fmaf(h, sWc[4 * DD + c], l4);
                        float pr = (i ? q2[s].y : q2[s].x) * (i ? kf.y : kf.x);
                        if (c < 75) a0 += pr;
                        else if (c < 150) a1 += pr;
                        else if (c < 225) a2 += pr;
                        else a3 += pr;
                    }
                }
            }

            #pragma unroll
            for (int o = 16; o; o >>= 1) {
                l0 += __shfl_xor_sync(FULL, l0, o);
                l1 += __shfl_xor_sync(FULL, l1, o);
                l2 += __shfl_xor_sync(FULL, l2, o);
                l3 += __shfl_xor_sync(FULL, l3, o);
                l4 += __shfl_xor_sync(FULL, l4, o);
                a0 += __shfl_xor_sync(FULL, a0, o);
                a1 += __shfl_xor_sync(FULL, a1, o);
                a2 += __shfl_xor_sync(FULL, a2, o);
                a3 += __shfl_xor_sync(FULL, a3, o);
            }
            // softmax without max-subtraction (logits bounded, safe)
            float p0 = __expf(l0 + sBcls[0]), p1 = __expf(l1 + sBcls[1]);
            float p2 = __expf(l2 + sBcls[2]), p3 = __expf(l3 + sBcls[3]);
            float p4 = __expf(l4 + sBcls[4]);
            float inv = __fdividef(1.0f, p0 + p1 + p2 + p3 + p4);
            p0 *= inv; p1 *= inv; p2 *= inv; p3 *= inv; p4 *= inv;
            float t0 = ea.x > 0.0f ? 1.0f : 0.0f;
            float t1 = ea.y < 0.0f ? 1.0f : 0.0f;

            float pj = (oj == 0) ? p0 : (oj == 1) ? p1 : (oj == 2) ? p2 : (oj == 3) ? p3
                      : (oj == 4) ? p4 : (oj == 5) ? t0 : (oj == 6) ? t1 : 1.0f;

            float qef = pj * QG;
            qef += __shfl_xor_sync(FULL, qef, 1, 8);
            qef += __shfl_xor_sync(FULL, qef, 2, 8);
            qef += __shfl_xor_sync(FULL, qef, 4, 8);

            float ah = (oh == 0) ? a0 : (oh == 1) ? a1 : (oh == 2) ? a2 : a3;
            float wv = __expf((ah + qef) * sc);

            float w0 = __shfl_sync(FULL, wv, 0);
            float w1 = __shfl_sync(FULL, wv, 8);
            float w2h = __shfl_sync(FULL, wv, 16);
            float w3h = __shfl_sync(FULL, wv, 24);

            Tacc = fmaf(wv, pj, Tacc);

            #pragma unroll
            for (int s = 0; s < 5; s++) {
                int col = 2 * lane + 64 * s;
                if (col < DD) {
                    float wa = col < 75 ? w0 : (col < 150 ? w1 : (col < 225 ? w2h : w3h));
                    int c1 = col + 1;
                    float wb = c1 < 75 ? w0 : (c1 < 150 ? w1 : (c1 < 225 ? w2h : w3h));
                    av[s].x = fmaf(wa, vf0[s], av[s].x);
                    av[s].y = fmaf(wb, vf1[s], av[s].y);
                }
            }
        }

        #pragma unroll
        for (int s = 0; s < 5; s++) {
            int col = 2 * lane + 64 * s;
            bool ok = col < DD;
            #pragma unroll
            for (int i = 0; i < 2; i++) {
                int cc = ok ? col + i : 0;
                int h = cc < 75 ? 0 : (cc < 150 ? 1 : (cc < 225 ? 2 : 3));
                int base = h * 8;
                float add = i ? av[s].y : av[s].x;
                float den = 0.0f;
                #pragma unroll
                for (int jj = 0; jj < 8; jj++) {
                    float tv = __shfl_sync(FULL, Tacc, base + jj);
                    add = fmaf(tv, sG[jj * DD + cc], add);
                    if (jj == 7) den = tv;
                }
                if (ok) {
                    float invd = den > 0.0f ? __fdividef(1.0f, den) : 0.0f;
                    out[(size_t)n * DD + cc] += add * invd;
                }
            }
        }
    }
}

// ---------------- host launcher ----------------
extern "C" void kernel_launch(void* const* d_in, const int* in_sizes, int n_in,
                              void* d_out, int out_size) {
    const float* x     = (const float*)d_in[0];
    const int*   EI    = (const int*)d_in[1];
    const float* EA    = (const float*)d_in[2];
    const float* nrm   = (const float*)d_in[3];
    const float* Wq    = (const float*)d_in[4];
    const float* bq    = (const float*)d_in[5];
    const float* Wk    = (const float*)d_in[6];
    const float* bk    = (const float*)d_in[7];
    const float* Wv    = (const float*)d_in[8];
    const float* bv    = (const float*)d_in[9];
    const float* We    = (const float*)d_in[10];
    const float* Wn    = (const float*)d_in[11];
    const float* bn    = (const float*)d_in[12];
    const float* Wxy   = (const float*)d_in[13];
    const float* bxy   = (const float*)d_in[14];
    const float* Wloc  = (const float*)d_in[15];
    const float* bloc  = (const float*)d_in[16];
    const float* Wobj  = (const float*)d_in[17];
    const float* bobj  = (const float*)d_in[18];
    const float* Wfus  = (const float*)d_in[19];
    const float* bfus  = (const float*)d_in[20];
    const float* Wcls  = (const float*)d_in[21];
    const float* bcls  = (const float*)d_in[22];
    const float* Wskip = (const float*)d_in[23];
    const float* bskip = (const float*)d_in[24];
    const float* vocab = (const float*)d_in[25];

    int Nn = in_sizes[0] / DD;
    int Ee = in_sizes[1] / 2;
    float* out = (float*)d_out;

    static bool init_done = false;
    static cudaStream_t s2;
    static cudaEvent_t ev0, ev1;
    const int gemm_smem = STAGES * (128 * 40 + 128 * 40) * 2;   // 61440 B
    if (!init_done) {
        cudaFuncSetAttribute(gemm_fp16_kernel, cudaFuncAttributeMaxDynamicSharedMemorySize, gemm_smem);
        cudaStreamCreateWithFlags(&s2, cudaStreamNonBlocking);
        cudaEventCreateWithFlags(&ev0, cudaEventDisableTiming);
        cudaEventCreateWithFlags(&ev1, cudaEventDisableTiming);
        init_done = true;
    }

    cudaEventRecord(ev0, 0);
    cudaStreamWaitEvent(s2, ev0, 0);
    int NB = (Nn + 255) / 256;
    zerodeg_kernel<<<NB, 256, 0, s2>>>(Nn);
    hist_kernel<<<(Ee + 255) / 256, 256, 0, s2>>>(EI, Ee);
    scan1_kernel<<<NB, 256, 0, s2>>>(Nn);
    scan2_kernel<<<1, 256, 0, s2>>>(NB);
    scan3_kernel<<<NB, 256, 0, s2>>>(Nn);
    scatter_kernel<<<(Ee + 255) / 256, 256, 0, s2>>>(EI, Ee);
    cudaEventRecord(ev1, s2);

    fold1b_kernel<<<DD, 128>>>(Wn, Wxy, Wloc, Wfus, vocab, bxy, bn, bobj, bloc, bfus);
    fold2b_kernel<<<DD, 64>>>(We);
    buildA_kernel<<<(Nn * 304 + 255) / 256, 256>>>(x, nrm, Nn);
    buildW_kernel<<<(NCOLS * 304 + 255) / 256, 256>>>(Wq, Wk, Wv, Wskip, Wobj, bq, bk, bv, bskip);

    dim3 gg(15, MPAD / 128);
    gemm_fp16_kernel<<<gg, 256, gemm_smem>>>(out, Nn);

    cudaStreamWaitEvent(0, ev1, 0);
    edgeF_kernel<<<1480, 128>>>(EA, Wcls, bcls, out, Nn);
}

// round 15
// speedup vs baseline: 1.4839x; 1.4839x over previous
#include <cuda_runtime.h>
#include <cuda_fp16.h>
#include <mma.h>
#include <math.h>
#include <stdint.h>

using namespace nvcuda;

#define DD 300
#define NCOLS 1800
#define KK2 320
#define MAXN 50000
#define MAXE 250000
#define MPAD 50048
#define STAGES 3
#define KT 32
#define NT (KK2 / KT)
#define SFST 608            // d_Sf (fp16): Q[0..300), Cd[304..604)
#define SHST 960            // d_Sh (fp16): K[0..300), V[320..620), Cs[640..940)

__device__ __half d_Ah[(size_t)MPAD * KK2];
__device__ __half d_WhT[(size_t)1920 * KK2];
__device__ __half d_Sf[(size_t)MPAD * SFST];
__device__ __half d_Sh[(size_t)MPAD * SHST];
__device__ float  d_NLi[3 * DD];
__device__ float  d_NLj[3 * DD];
__device__ float  d_W2f[2 * DD];
__device__ float  d_c0[DD];
__device__ float  d_T8[8 * DD];
__device__ float  d_G8[8 * DD];
__device__ int  d_deg[MAXN];
__device__ int  d_rowptr[MAXN + 1];
__device__ int  d_cursor[MAXN];
__device__ int  d_blksum[256];
__device__ int2 d_edges[MAXE];

__device__ __forceinline__ float fast_tanh(float x) {
    float r;
    asm("tanh.approx.f32 %0, %1;" : "=f"(r) : "f"(x));
    return r;
}

// ---------------- fold1b ----------------
__global__ void __launch_bounds__(128) fold1b_kernel(
        const float* __restrict__ Wn, const float* __restrict__ Wxy,
        const float* __restrict__ Wloc, const float* __restrict__ Wfus,
        const float* __restrict__ vocab, const float* __restrict__ bxy,
        const float* __restrict__ bn, const float* __restrict__ bobj,
        const float* __restrict__ bloc, const float* __restrict__ bfus) {
    int c = blockIdx.x;
    int t = threadIdx.x;
    float pt[16];
    #pragma unroll
    for (int j = 0; j < 16; j++) pt[j] = 0.0f;

    for (int k = t; k < DD; k += 128) {
        float wl0 = Wloc[k * DD + c];
        float wl1 = Wloc[(DD + k) * DD + c];
        float wl2 = Wloc[(2 * DD + k) * DD + c];
        float wn0 = Wn[k], wn1 = Wn[DD + k], wn2 = Wn[2 * DD + k];
        pt[0] = fmaf(wn0, wl1, pt[0]); pt[1] = fmaf(wn1, wl1, pt[1]); pt[2] = fmaf(wn2, wl1, pt[2]);
        pt[3] = fmaf(wn0, wl2, pt[3]); pt[4] = fmaf(wn1, wl2, pt[4]); pt[5] = fmaf(wn2, wl2, pt[5]);
        pt[6] = fmaf(Wxy[k], wl0, pt[6]); pt[7] = fmaf(Wxy[DD + k], wl0, pt[7]);
        pt[8] = fmaf(bxy[k], wl0, pt[8]);
        pt[8] = fmaf(bn[k], wl1 + wl2, pt[8]);
        float wf0 = Wfus[k * DD + c];
        float wf1 = Wfus[(DD + k) * DD + c];
        pt[9]  = fmaf(vocab[2 * DD + k], wf1, pt[9]);
        pt[10] = fmaf(vocab[3 * DD + k], wf1, pt[10]);
        pt[11] = fmaf(vocab[4 * DD + k], wf1, pt[11]);
        pt[12] = fmaf(vocab[5 * DD + k], wf1, pt[12]);
        pt[13] = fmaf(vocab[6 * DD + k], wf1, pt[13]);
        pt[14] = fmaf(vocab[k], wf0, pt[14]);
        pt[15] = fmaf(vocab[DD + k], wf0, pt[15]);
    }

    __shared__ float sd[16][128];
    #pragma unroll
    for (int j = 0; j < 16; j++) sd[j][t] = pt[j];
    __syncthreads();
    #pragma unroll
    for (int off = 64; off; off >>= 1) {
        if (t < off) {
            #pragma unroll
            for (int j = 0; j < 16; j++) sd[j][t] += sd[j][t + off];
        }
        __syncthreads();
    }
    if (t == 0) {
        d_NLi[0 * DD + c] = sd[0][0]; d_NLi[1 * DD + c] = sd[1][0]; d_NLi[2 * DD + c] = sd[2][0];
        d_NLj[0 * DD + c] = sd[3][0]; d_NLj[1 * DD + c] = sd[4][0]; d_NLj[2 * DD + c] = sd[5][0];
        d_W2f[c] = sd[6][0]; d_W2f[DD + c] = sd[7][0];
        d_c0[c] = sd[8][0] + bobj[c] + bloc[c];
        d_T8[0 * DD + c] = sd[9][0];  d_T8[1 * DD + c] = sd[10][0];
        d_T8[2 * DD + c] = sd[11][0]; d_T8[3 * DD + c] = sd[12][0];
        d_T8[4 * DD + c] = sd[13][0]; d_T8[5 * DD + c] = sd[14][0];
        d_T8[6 * DD + c] = sd[15][0]; d_T8[7 * DD + c] = bfus[c];
    }
}

// ---------------- fold2b ----------------
__global__ void __launch_bounds__(64) fold2b_kernel(const float* __restrict__ We) {
    int c = blockIdx.x;
    int t = threadIdx.x;
    float g[8];
    #pragma unroll
    for (int j = 0; j < 8; j++) g[j] = 0.0f;
    for (int k = t; k < DD; k += 64) {
        float w = We[k * DD + c];
        #pragma unroll
        for (int j = 0; j < 8; j++) g[j] = fmaf(d_T8[j * DD + k], w, g[j]);
    }
    __shared__ float sd[8][64];
    #pragma unroll
    for (int j = 0; j < 8; j++) sd[j][t] = g[j];
    __syncthreads();
    #pragma unroll
    for (int off = 32; off; off >>= 1) {
        if (t < off) {
            #pragma unroll
            for (int j = 0; j < 8; j++) sd[j][t] += sd[j][t + off];
        }
        __syncthreads();
    }
    if (t == 0) {
        #pragma unroll
        for (int j = 0; j < 8; j++) d_G8[j * DD + c] = sd[j][0];
    }
}

// ---------------- build A ----------------
__global__ void buildA_kernel(const float* __restrict__ x, const float* __restrict__ nrm, int Nn) {
    int idx = blockIdx.x * blockDim.x + threadIdx.x;
    if (idx >= Nn * 304) return;
    int n = idx / 304, k = idx - n * 304;
    float v;
    if (k < DD) v = x[n * DD + k];
    else if (k < DD + 3) v = nrm[n * 3 + (k - DD)];
    else v = 1.0f;
    d_Ah[(size_t)n * KK2 + k] = __float2half_rn(v);
}

// ---------------- build WhT ----------------
__global__ void buildW_kernel(const float* __restrict__ Wq, const float* __restrict__ Wk,
                              const float* __restrict__ Wv, const float* __restrict__ Wskip,
                              const float* __restrict__ Wobj, const float* __restrict__ bq,
                              const float* __restrict__ bk, const float* __restrict__ bv,
                              const float* __restrict__ bskip) {
    int idx = blockIdx.x * blockDim.x + threadIdx.x;
    if (idx >= NCOLS * 304) return;
    int c = idx / 304, k = idx - c * 304;
    int b = c / DD, cc = c - b * DD;
    float v = 0.0f;
    if (k < DD) {
        if (b == 0) v = Wq[k * DD + cc];
        else if (b == 1) v = Wk[k * DD + cc];
        else if (b == 2) v = Wv[k * DD + cc];
        else if (b == 3) v = Wskip[k * DD + cc];
        else if (b == 4) v = Wobj[k * DD + cc] - Wobj[(DD + k) * DD + cc];
        else v = Wobj[(DD + k) * DD + cc];
    } else if (k < DD + 3) {
        int r = k - DD;
        if (b == 4) v = d_NLi[r * DD + cc];
        else if (b == 5) v = d_NLj[r * DD + cc];
    } else {
        if (b == 0) v = bq[cc];
        else if (b == 1) v = bk[cc];
        else if (b == 2) v = bv[cc];
        else if (b == 3) v = bskip[cc];
        else if (b == 4) v = d_c0[cc];
    }
    d_WhT[(size_t)c * KK2 + k] = __float2half_rn(v);
}

// ---------------- node GEMM: 3-stage, 3 CTAs/SM, two-pass epilogue ----------------
__global__ void __launch_bounds__(256, 3) gemm_fp16_kernel(float* __restrict__ out, int Nn) {
    extern __shared__ __half sm[];
    __half (*As)[128][40] = (__half (*)[128][40])sm;
    __half (*Bs)[128][40] = (__half (*)[128][40])(sm + STAGES * 128 * 40);
    float (*stage)[132] = (float (*)[132])sm;   // 64 x 132 epilogue reuse

    int tid = threadIdx.x;
    int wid = tid >> 5;
    int wm = wid >> 2;
    int wn = wid & 3;
    int row0 = blockIdx.y * 128, col0 = blockIdx.x * 128;

    wmma::fragment<wmma::accumulator, 16, 16, 16, float> acc[4][2];
    #pragma unroll
    for (int i = 0; i < 4; i++)
        #pragma unroll
        for (int j = 0; j < 2; j++) wmma::fill_fragment(acc[i][j], 0.0f);

    auto loadStage = [&](int st, int kt) {
        #pragma unroll
        for (int u = 0; u < 2; u++) {
            int idx = tid + 256 * u;
            int row = idx >> 2, seg = idx & 3;
            const __half* ga = &d_Ah[(size_t)(row0 + row) * KK2 + kt + seg * 8];
            uint32_t da = (uint32_t)__cvta_generic_to_shared(&As[st][row][seg * 8]);
            asm volatile("cp.async.cg.shared.global [%0], [%1], 16;" :: "r"(da), "l"(ga));
            const __half* gb = &d_WhT[(size_t)(col0 + row) * KK2 + kt + seg * 8];
            uint32_t db = (uint32_t)__cvta_generic_to_shared(&Bs[st][row][seg * 8]);
            asm volatile("cp.async.cg.shared.global [%0], [%1], 16;" :: "r"(db), "l"(gb));
        }
    };

    #pragma unroll
    for (int i = 0; i < STAGES - 1; i++) {
        loadStage(i, i * KT);
        asm volatile("cp.async.commit_group;");
    }

    int stq = 0;
    for (int s = 0; s < NT; s++) {
        asm volatile("cp.async.wait_group %0;" :: "n"(STAGES - 2));
        __syncthreads();
        int ld = s + STAGES - 1;
        if (ld < NT) {
            int st = (stq + STAGES - 1) % STAGES;
            loadStage(st, ld * KT);
        }
        asm volatile("cp.async.commit_group;");

        int st = stq;
        #pragma unroll
        for (int ks = 0; ks < 2; ks++) {
            int k0 = ks * 16;
            wmma::fragment<wmma::matrix_b, 16, 16, 16, __half, wmma::col_major> bf[2];
            #pragma unroll
            for (int j = 0; j < 2; j++)
                wmma::load_matrix_sync(bf[j], &Bs[st][wn * 32 + j * 16][k0], 40);
            #pragma unroll
            for (int i = 0; i < 4; i++) {
                wmma::fragment<wmma::matrix_a, 16, 16, 16, __half, wmma::row_major> af;
                wmma::load_matrix_sync(af, &As[st][wm * 64 + i * 16][k0], 40);
                #pragma unroll
                for (int j = 0; j < 2; j++)
                    wmma::mma_sync(acc[i][j], af, bf[j], acc[i][j]);
            }
        }
        stq++;
        if (stq == STAGES) stq = 0;
    }

    asm volatile("cp.async.wait_group 0;");
    __syncthreads();

    // two-pass epilogue: pass h stages rows [h*64, h*64+64)
    #pragma unroll
    for (int hp = 0; hp < 2; hp++) {
        if (wm == hp) {
            #pragma unroll
            for (int i = 0; i < 4; i++)
                #pragma unroll
                for (int j = 0; j < 2; j++)
                    wmma::store_matrix_sync(&stage[i * 16][wn * 32 + j * 16],
                                            acc[i][j], 132, wmma::mem_row_major);
        }
        __syncthreads();
        #pragma unroll
        for (int it = 0; it < 8; it++) {
            int idx = tid + it * 256;        // 0..2047 (64 rows x 32 groups)
            int r = idx >> 5;
            int c4 = (idx & 31) * 4;
            int gc = col0 + c4;
            if (gc < NCOLS) {
                int n = row0 + hp * 64 + r;
                float4 v = *(float4*)&stage[r][c4];
                int b = gc / DD;
                int cc = gc - b * DD;
                if (b == 3) {
                    if (n < Nn) *(float4*)&out[(size_t)n * DD + cc] = v;
                } else {
                    __half2 h0 = __floats2half2_rn(v.x, v.y);
                    __half2 h1 = __floats2half2_rn(v.z, v.w);
                    uint2 u = make_uint2(*(uint32_t*)&h0, *(uint32_t*)&h1);
                    if (b == 0) {
                        *(uint2*)&d_Sf[(size_t)n * SFST + cc] = u;
                    } else if (b == 4) {
                        *(uint2*)&d_Sf[(size_t)n * SFST + 304 + cc] = u;
                    } else {
                        int off = (b == 1) ? 0 : (b == 2 ? 320 : 640);
                        *(uint2*)&d_Sh[(size_t)n * SHST + off + cc] = u;
                    }
                }
            }
        }
        __syncthreads();
    }
}

// ---------------- CSR build ----------------
__global__ void zerodeg_kernel(int Nn) {
    int i = blockIdx.x * blockDim.x + threadIdx.x;
    if (i < Nn) d_deg[i] = 0;
}
__global__ void hist_kernel(const int* __restrict__ EI, int Ee) {
    int e = blockIdx.x * blockDim.x + threadIdx.x;
    if (e < Ee) atomicAdd(&d_deg[EI[Ee + e]], 1);
}
__global__ void scan1_kernel(int Nn) {
    __shared__ int sdata[256];
    int t = threadIdx.x;
    int i = blockIdx.x * 256 + t;
    int v = (i < Nn) ? d_deg[i] : 0;
    sdata[t] = v;
    __syncthreads();
    #pragma unroll
    for (int off = 1; off < 256; off <<= 1) {
        int x = (t >= off) ? sdata[t - off] : 0;
        __syncthreads();
        sdata[t] += x;
        __syncthreads();
    }
    if (i < Nn) d_rowptr[i] = sdata[t] - v;
    if (t == 255) d_blksum[blockIdx.x] = sdata[255];
}
__global__ void scan2_kernel(int NB) {
    __shared__ int sdata[256];
    int t = threadIdx.x;
    int v = (t < NB) ? d_blksum[t] : 0;
    sdata[t] = v;
    __syncthreads();
    #pragma unroll
    for (int off = 1; off < 256; off <<= 1) {
        int x = (t >= off) ? sdata[t - off] : 0;
        __syncthreads();
        sdata[t] += x;
        __syncthreads();
    }
    if (t < NB) d_blksum[t] = sdata[t] - v;
}
__global__ void scan3_kernel(int Nn) {
    int i = blockIdx.x * blockDim.x + threadIdx.x;
    if (i >= Nn) return;
    int val = d_rowptr[i] + d_blksum[i >> 8];
    d_rowptr[i] = val;
    d_cursor[i] = val;
    if (i == Nn - 1) d_rowptr[Nn] = val + d_deg[i];
}
__global__ void scatter_kernel(const int* __restrict__ EI, int Ee) {
    int e = blockIdx.x * blockDim.x + threadIdx.x;
    if (e >= Ee) return;
    int dst = EI[Ee + e];
    int pos = atomicAdd(&d_cursor[dst], 1);
    d_edges[pos] = make_int2(EI[e], e);
}

// ---------------- edgeF v5: no max-subtraction ----------------
__global__ void __launch_bounds__(128, 5) edgeF_kernel(const float* __restrict__ EA,
                                                       const float* __restrict__ Wcls,
                                                       const float* __restrict__ bcls,
                                                       float* __restrict__ out, int Nn) {
    __shared__ float sWc[5 * DD];
    __shared__ float sG[8 * DD];
    __shared__ float2 sW2[DD];
    __shared__ float sBcls[5];
    for (int i = threadIdx.x; i < 5 * DD; i += 128) {
        int k = i / DD, c = i - k * DD;
        sWc[i] = Wcls[c * 5 + k];
    }
    for (int i = threadIdx.x; i < 8 * DD; i += 128) sG[i] = d_G8[i];
    for (int i = threadIdx.x; i < DD; i += 128)
        sW2[i] = make_float2(d_W2f[i], d_W2f[DD + i]);
    if (threadIdx.x < 5) sBcls[threadIdx.x] = bcls[threadIdx.x];
    __syncthreads();

    const uint32_t FULL = 0xffffffffu;
    int lane = threadIdx.x & 31;
    int warp = threadIdx.x >> 5;
    int oh = lane >> 3, oj = lane & 7;
    const float sc = 0.115470053837925152f;  // 1/sqrt(75)

    for (int n = blockIdx.x * 4 + warp; n < Nn; n += gridDim.x * 4) {
        int beg = d_rowptr[n], end = d_rowptr[n + 1];
        const __half* rowQ = d_Sf + (size_t)n * SFST;

        float QG = 0.0f;
        {
            const __half* qb = rowQ + oh * 75;
            const float* gb = sG + oj * DD + oh * 75;
            #pragma unroll 5
            for (int c = 0; c < 75; c++)
                QG = fmaf(__half2float(__ldg(&qb[c])), gb[c], QG);
        }

        float2 q2[5], cd2[5], av[5];
        #pragma unroll
        for (int s = 0; s < 5; s++) {
            int col = 2 * lane + 64 * s;
            bool ok = col < DD;
            if (ok) {
                q2[s]  = __half22float2(*(const __half2*)(rowQ + col));
                cd2[s] = __half22float2(*(const __half2*)(rowQ + 304 + col));
            } else {
                q2[s] = make_float2(0, 0);
                cd2[s] = make_float2(0, 0);
            }
            av[s] = make_float2(0, 0);
        }
        float Tacc = 0.0f;

        for (int p = beg; p < end; p++) {
            int2 se = __ldg(&d_edges[p]);
            const __half* rowS = d_Sh + (size_t)se.x * SHST;
            float4 ea = __ldg((const float4*)&EA[4 * se.y]);

            uint32_t kh[5], vh[5], ch[5];
            #pragma unroll
            for (int s = 0; s < 5; s++) {
                int col = 2 * lane + 64 * s;
                bool ok = col < DD;
                kh[s] = ok ? __ldg((const uint32_t*)(rowS + col)) : 0u;
                vh[s] = ok ? __ldg((const uint32_t*)(rowS + 320 + col)) : 0u;
                ch[s] = ok ? __ldg((const uint32_t*)(rowS + 640 + col)) : 0u;
            }

            float vf0[5], vf1[5];
            float l0 = 0, l1 = 0, l2 = 0, l3 = 0, l4 = 0;
            float a0 = 0, a1 = 0, a2 = 0, a3 = 0;
            #pragma unroll
            for (int s = 0; s < 5; s++) {
                int col = 2 * lane + 64 * s;
                float2 kf = __half22float2(*(__half2*)&kh[s]);
                float2 vf = __half22float2(*(__half2*)&vh[s]);
                float2 cf = __half22float2(*(__half2*)&ch[s]);
                vf0[s] = vf.x; vf1[s] = vf.y;
                if (col < DD) {
                    #pragma unroll
                    for (int i = 0; i < 2; i++) {
                        int c = col + i;
                        float2 w2 = sW2[c];
                        float cdv = i ? cd2[s].y : cd2[s].x;
                        float csv = i ? cf.y : cf.x;
                        float h = fast_tanh(cdv + csv + ea.z * w2.x + ea.w * w2.y);
                        l0 = fmaf(h, sWc[c], l0);
                        l1 = fmaf(h, sWc[DD + c], l1);
                        l2 = fmaf(h, sWc[2 * DD + c], l2);
                        l3 = fmaf(h, sWc[3 * DD + c], l3);
                        l4 = fmaf(h, sWc[4 * DD + c], l4);
                        float pr = (i ? q2[s].y : q2[s].x) * (i ? kf.y : kf.x);
                        if (c < 75) a0 += pr;
                        else if (c < 150) a1 += pr;
                        else if (c < 225) a2 += pr;
                        else a3 += pr;
                    }
                }
            }

            #pragma unroll
            for (int o = 16; o; o >>= 1) {
                l0 += __shfl_xor_sync(FULL, l0, o);
                l1 += __shfl_xor_sync(FULL, l1, o);
                l2 += __shfl_xor_sync(FULL, l2, o);
                l3 += __shfl_xor_sync(FULL, l3, o);
                l4 += __shfl_xor_sync(FULL, l4, o);
                a0 += __shfl_xor_sync(FULL, a0, o);
                a1 += __shfl_xor_sync(FULL, a1, o);
                a2 += __shfl_xor_sync(FULL, a2, o);
                a3 += __shfl_xor_sync(FULL, a3, o);
            }
            // softmax without max-subtraction (logits bounded, safe)
            float p0 = __expf(l0 + sBcls[0]), p1 = __expf(l1 + sBcls[1]);
            float p2 = __expf(l2 + sBcls[2]), p3 = __expf(l3 + sBcls[3]);
            float p4 = __expf(l4 + sBcls[4]);
            float inv = __fdividef(1.0f, p0 + p1 + p2 + p3 + p4);
            p0 *= inv; p1 *= inv; p2 *= inv; p3 *= inv; p4 *= inv;
            float t0 = ea.x > 0.0f ? 1.0f : 0.0f;
            float t1 = ea.y < 0.0f ? 1.0f : 0.0f;

            float pj = (oj == 0) ? p0 : (oj == 1) ? p1 : (oj == 2) ? p2 : (oj == 3) ? p3
                      : (oj == 4) ? p4 : (oj == 5) ? t0 : (oj == 6) ? t1 : 1.0f;

            float qef = pj * QG;
            qef += __shfl_xor_sync(FULL, qef, 1, 8);
            qef += __shfl_xor_sync(FULL, qef, 2, 8);
            qef += __shfl_xor_sync(FULL, qef, 4, 8);

            float ah = (oh == 0) ? a0 : (oh == 1) ? a1 : (oh == 2) ? a2 : a3;
            float wv = __expf((ah + qef) * sc);

            float w0 = __shfl_sync(FULL, wv, 0);
            float w1 = __shfl_sync(FULL, wv, 8);
            float w2h = __shfl_sync(FULL, wv, 16);
            float w3h = __shfl_sync(FULL, wv, 24);

            Tacc = fmaf(wv, pj, Tacc);

            #pragma unroll
            for (int s = 0; s < 5; s++) {
                int col = 2 * lane + 64 * s;
                if (col < DD) {
                    float wa = col < 75 ? w0 : (col < 150 ? w1 : (col < 225 ? w2h : w3h));
                    int c1 = col + 1;
                    float wb = c1 < 75 ? w0 : (c1 < 150 ? w1 : (c1 < 225 ? w2h : w3h));
                    av[s].x = fmaf(wa, vf0[s], av[s].x);
                    av[s].y = fmaf(wb, vf1[s], av[s].y);
                }
            }
        }

        #pragma unroll
        for (int s = 0; s < 5; s++) {
            int col = 2 * lane + 64 * s;
            bool ok = col < DD;
            #pragma unroll
            for (int i = 0; i < 2; i++) {
                int cc = ok ? col + i : 0;
                int h = cc < 75 ? 0 : (cc < 150 ? 1 : (cc < 225 ? 2 : 3));
                int base = h * 8;
                float add = i ? av[s].y : av[s].x;
                float den = 0.0f;
                #pragma unroll
                for (int jj = 0; jj < 8; jj++) {
                    float tv = __shfl_sync(FULL, Tacc, base + jj);
                    add = fmaf(tv, sG[jj * DD + cc], add);
                    if (jj == 7) den = tv;
                }
                if (ok) {
                    float invd = den > 0.0f ? __fdividef(1.0f, den) : 0.0f;
                    out[(size_t)n * DD + cc] += add * invd;
                }
            }
        }
    }
}

// ---------------- host launcher ----------------
extern "C" void kernel_launch(void* const* d_in, const int* in_sizes, int n_in,
                              void* d_out, int out_size) {
    const float* x     = (const float*)d_in[0];
    const int*   EI    = (const int*)d_in[1];
    const float* EA    = (const float*)d_in[2];
    const float* nrm   = (const float*)d_in[3];
    const float* Wq    = (const float*)d_in[4];
    const float* bq    = (const float*)d_in[5];
    const float* Wk    = (const float*)d_in[6];
    const float* bk    = (const float*)d_in[7];
    const float* Wv    = (const float*)d_in[8];
    const float* bv    = (const float*)d_in[9];
    const float* We    = (const float*)d_in[10];
    const float* Wn    = (const float*)d_in[11];
    const float* bn    = (const float*)d_in[12];
    const float* Wxy   = (const float*)d_in[13];
    const float* bxy   = (const float*)d_in[14];
    const float* Wloc  = (const float*)d_in[15];
    const float* bloc  = (const float*)d_in[16];
    const float* Wobj  = (const float*)d_in[17];
    const float* bobj  = (const float*)d_in[18];
    const float* Wfus  = (const float*)d_in[19];
    const float* bfus  = (const float*)d_in[20];
    const float* Wcls  = (const float*)d_in[21];
    const float* bcls  = (const float*)d_in[22];
    const float* Wskip = (const float*)d_in[23];
    const float* bskip = (const float*)d_in[24];
    const float* vocab = (const float*)d_in[25];

    int Nn = in_sizes[0] / DD;
    int Ee = in_sizes[1] / 2;
    float* out = (float*)d_out;

    static bool init_done = false;
    static cudaStream_t s2;
    static cudaEvent_t ev0, ev1;
    const int gemm_smem = STAGES * (128 * 40 + 128 * 40) * 2;   // 61440 B
    if (!init_done) {
        cudaFuncSetAttribute(gemm_fp16_kernel, cudaFuncAttributeMaxDynamicSharedMemorySize, gemm_smem);
        cudaStreamCreateWithFlags(&s2, cudaStreamNonBlocking);
        cudaEventCreateWithFlags(&ev0, cudaEventDisableTiming);
        cudaEventCreateWithFlags(&ev1, cudaEventDisableTiming);
        init_done = true;
    }

    cudaEventRecord(ev0, 0);
    cudaStreamWaitEvent(s2, ev0, 0);
    int NB = (Nn + 255) / 256;
    zerodeg_kernel<<<NB, 256, 0, s2>>>(Nn);
    hist_kernel<<<(Ee + 255) / 256, 256, 0, s2>>>(EI, Ee);
    scan1_kernel<<<NB, 256, 0, s2>>>(Nn);
    scan2_kernel<<<1, 256, 0, s2>>>(NB);
    scan3_kernel<<<NB, 256, 0, s2>>>(Nn);
    scatter_kernel<<<(Ee + 255) / 256, 256, 0, s2>>>(EI, Ee);
    cudaEventRecord(ev1, s2);

    fold1b_kernel<<<DD, 128>>>(Wn, Wxy, Wloc, Wfus, vocab, bxy, bn, bobj, bloc, bfus);
    fold2b_kernel<<<DD, 64>>>(We);
    buildA_kernel<<<(Nn * 304 + 255) / 256, 256>>>(x, nrm, Nn);
    buildW_kernel<<<(NCOLS * 304 + 255) / 256, 256>>>(Wq, Wk, Wv, Wskip, Wobj, bq, bk, bv, bskip);

    dim3 gg(15, MPAD / 128);
    gemm_fp16_kernel<<<gg, 256, gemm_smem>>>(out, Nn);

    cudaStreamWaitEvent(0, ev1, 0);
    edgeF_kernel<<<1480, 128>>>(EA, Wcls, bcls, out, Nn);
}

// round 16
// speedup vs baseline: 1.4903x; 1.0043x over previous
#include <cuda_runtime.h>
#include <cuda_fp16.h>
#include <mma.h>
#include <math.h>
#include <stdint.h>

using namespace nvcuda;

#define DD 300
#define NCOLS 1800
#define KK2 320
#define MAXN 50000
#define MAXE 250000
#define MPAD 50048
#define STAGES 3
#define KT 32
#define NT (KK2 / KT)
#define SFST 608            // d_Sf (fp16): Q[0..300), Cd[304..604)
#define SHST 960            // d_Sh (fp16): K[0..300), V[320..620), Cs[640..940)

__device__ __half d_Ah[(size_t)MPAD * KK2];
__device__ __half d_WhT[(size_t)1920 * KK2];
__device__ __half d_Sf[(size_t)MPAD * SFST];
__device__ __half d_Sh[(size_t)MPAD * SHST];
__device__ float  d_NLi[3 * DD];
__device__ float  d_NLj[3 * DD];
__device__ float  d_W2f[2 * DD];
__device__ float  d_c0[DD];
__device__ float  d_T8[8 * DD];
__device__ float  d_G8[8 * DD];
__device__ int  d_deg[MAXN];
__device__ int  d_rowptr[MAXN + 1];
__device__ int  d_cursor[MAXN];
__device__ int  d_blksum[256];
__device__ int2 d_edges[MAXE];

__device__ __forceinline__ float fast_tanh(float x) {
    float r;
    asm("tanh.approx.f32 %0, %1;" : "=f"(r) : "f"(x));
    return r;
}

// ---------------- fold1b ----------------
__global__ void __launch_bounds__(128) fold1b_kernel(
        const float* __restrict__ Wn, const float* __restrict__ Wxy,
        const float* __restrict__ Wloc, const float* __restrict__ Wfus,
        const float* __restrict__ vocab, const float* __restrict__ bxy,
        const float* __restrict__ bn, const float* __restrict__ bobj,
        const float* __restrict__ bloc, const float* __restrict__ bfus) {
    int c = blockIdx.x;
    int t = threadIdx.x;
    float pt[16];
    #pragma unroll
    for (int j = 0; j < 16; j++) pt[j] = 0.0f;

    for (int k = t; k < DD; k += 128) {
        float wl0 = Wloc[k * DD + c];
        float wl1 = Wloc[(DD + k) * DD + c];
        float wl2 = Wloc[(2 * DD + k) * DD + c];
        float wn0 = Wn[k], wn1 = Wn[DD + k], wn2 = Wn[2 * DD + k];
        pt[0] = fmaf(wn0, wl1, pt[0]); pt[1] = fmaf(wn1, wl1, pt[1]); pt[2] = fmaf(wn2, wl1, pt[2]);
        pt[3] = fmaf(wn0, wl2, pt[3]); pt[4] = fmaf(wn1, wl2, pt[4]); pt[5] = fmaf(wn2, wl2, pt[5]);
        pt[6] = fmaf(Wxy[k], wl0, pt[6]); pt[7] = fmaf(Wxy[DD + k], wl0, pt[7]);
        pt[8] = fmaf(bxy[k], wl0, pt[8]);
        pt[8] = fmaf(bn[k], wl1 + wl2, pt[8]);
        float wf0 = Wfus[k * DD + c];
        float wf1 = Wfus[(DD + k) * DD + c];
        pt[9]  = fmaf(vocab[2 * DD + k], wf1, pt[9]);
        pt[10] = fmaf(vocab[3 * DD + k], wf1, pt[10]);
        pt[11] = fmaf(vocab[4 * DD + k], wf1, pt[11]);
        pt[12] = fmaf(vocab[5 * DD + k], wf1, pt[12]);
        pt[13] = fmaf(vocab[6 * DD + k], wf1, pt[13]);
        pt[14] = fmaf(vocab[k], wf0, pt[14]);
        pt[15] = fmaf(vocab[DD + k], wf0, pt[15]);
    }

    __shared__ float sd[16][128];
    #pragma unroll
    for (int j = 0; j < 16; j++) sd[j][t] = pt[j];
    __syncthreads();
    #pragma unroll
    for (int off = 64; off; off >>= 1) {
        if (t < off) {
            #pragma unroll
            for (int j = 0; j < 16; j++) sd[j][t] += sd[j][t + off];
        }
        __syncthreads();
    }
    if (t == 0) {
        d_NLi[0 * DD + c] = sd[0][0]; d_NLi[1 * DD + c] = sd[1][0]; d_NLi[2 * DD + c] = sd[2][0];
        d_NLj[0 * DD + c] = sd[3][0]; d_NLj[1 * DD + c] = sd[4][0]; d_NLj[2 * DD + c] = sd[5][0];
        d_W2f[c] = sd[6][0]; d_W2f[DD + c] = sd[7][0];
        d_c0[c] = sd[8][0] + bobj[c] + bloc[c];
        d_T8[0 * DD + c] = sd[9][0];  d_T8[1 * DD + c] = sd[10][0];
        d_T8[2 * DD + c] = sd[11][0]; d_T8[3 * DD + c] = sd[12][0];
        d_T8[4 * DD + c] = sd[13][0]; d_T8[5 * DD + c] = sd[14][0];
        d_T8[6 * DD + c] = sd[15][0]; d_T8[7 * DD + c] = bfus[c];
    }
}

// ---------------- fold2b ----------------
__global__ void __launch_bounds__(64) fold2b_kernel(const float* __restrict__ We) {
    int c = blockIdx.x;
    int t = threadIdx.x;
    float g[8];
    #pragma unroll
    for (int j = 0; j < 8; j++) g[j] = 0.0f;
    for (int k = t; k < DD; k += 64) {
        float w = We[k * DD + c];
        #pragma unroll
        for (int j = 0; j < 8; j++) g[j] = fmaf(d_T8[j * DD + k], w, g[j]);
    }
    __shared__ float sd[8][64];
    #pragma unroll
    for (int j = 0; j < 8; j++) sd[j][t] = g[j];
    __syncthreads();
    #pragma unroll
    for (int off = 32; off; off >>= 1) {
        if (t < off) {
            #pragma unroll
            for (int j = 0; j < 8; j++) sd[j][t] += sd[j][t + off];
        }
        __syncthreads();
    }
    if (t == 0) {
        #pragma unroll
        for (int j = 0; j < 8; j++) d_G8[j * DD + c] = sd[j][0];
    }
}

// ---------------- build A ----------------
__global__ void buildA_kernel(const float* __restrict__ x, const float* __restrict__ nrm, int Nn) {
    int idx = blockIdx.x * blockDim.x + threadIdx.x;
    if (idx >= Nn * 304) return;
    int n = idx / 304, k = idx - n * 304;
    float v;
    if (k < DD) v = x[n * DD + k];
    else if (k < DD + 3) v = nrm[n * 3 + (k - DD)];
    else v = 1.0f;
    d_Ah[(size_t)n * KK2 + k] = __float2half_rn(v);
}

// ---------------- build WhT ----------------
__global__ void buildW_kernel(const float* __restrict__ Wq, const float* __restrict__ Wk,
                              const float* __restrict__ Wv, const float* __restrict__ Wskip,
                              const float* __restrict__ Wobj, const float* __restrict__ bq,
                              const float* __restrict__ bk, const float* __restrict__ bv,
                              const float* __restrict__ bskip) {
    int idx = blockIdx.x * blockDim.x + threadIdx.x;
    if (idx >= NCOLS * 304) return;
    int c = idx / 304, k = idx - c * 304;
    int b = c / DD, cc = c - b * DD;
    float v = 0.0f;
    if (k < DD) {
        if (b == 0) v = Wq[k * DD + cc];
        else if (b == 1) v = Wk[k * DD + cc];
        else if (b == 2) v = Wv[k * DD + cc];
        else if (b == 3) v = Wskip[k * DD + cc];
        else if (b == 4) v = Wobj[k * DD + cc] - Wobj[(DD + k) * DD + cc];
        else v = Wobj[(DD + k) * DD + cc];
    } else if (k < DD + 3) {
        int r = k - DD;
        if (b == 4) v = d_NLi[r * DD + cc];
        else if (b == 5) v = d_NLj[r * DD + cc];
    } else {
        if (b == 0) v = bq[cc];
        else if (b == 1) v = bk[cc];
        else if (b == 2) v = bv[cc];
        else if (b == 3) v = bskip[cc];
        else if (b == 4) v = d_c0[cc];
    }
    d_WhT[(size_t)c * KK2 + k] = __float2half_rn(v);
}

// ---------------- node GEMM: 3-stage, 3 CTAs/SM, two-pass epilogue ----------------
__global__ void __launch_bounds__(256, 3) gemm_fp16_kernel(float* __restrict__ out, int Nn) {
    extern __shared__ __half sm[];
    __half (*As)[128][40] = (__half (*)[128][40])sm;
    __half (*Bs)[128][40] = (__half (*)[128][40])(sm + STAGES * 128 * 40);
    float (*stage)[132] = (float (*)[132])sm;   // 64 x 132 epilogue reuse

    int tid = threadIdx.x;
    int wid = tid >> 5;
    int wm = wid >> 2;
    int wn = wid & 3;
    int row0 = blockIdx.y * 128, col0 = blockIdx.x * 128;

    wmma::fragment<wmma::accumulator, 16, 16, 16, float> acc[4][2];
    #pragma unroll
    for (int i = 0; i < 4; i++)
        #pragma unroll
        for (int j = 0; j < 2; j++) wmma::fill_fragment(acc[i][j], 0.0f);

    auto loadStage = [&](int st, int kt) {
        #pragma unroll
        for (int u = 0; u < 2; u++) {
            int idx = tid + 256 * u;
            int row = idx >> 2, seg = idx & 3;
            const __half* ga = &d_Ah[(size_t)(row0 + row) * KK2 + kt + seg * 8];
            uint32_t da = (uint32_t)__cvta_generic_to_shared(&As[st][row][seg * 8]);
            asm volatile("cp.async.cg.shared.global [%0], [%1], 16;" :: "r"(da), "l"(ga));
            const __half* gb = &d_WhT[(size_t)(col0 + row) * KK2 + kt + seg * 8];
            uint32_t db = (uint32_t)__cvta_generic_to_shared(&Bs[st][row][seg * 8]);
            asm volatile("cp.async.cg.shared.global [%0], [%1], 16;" :: "r"(db), "l"(gb));
        }
    };

    #pragma unroll
    for (int i = 0; i < STAGES - 1; i++) {
        loadStage(i, i * KT);
        asm volatile("cp.async.commit_group;");
    }

    int stq = 0;
    for (int s = 0; s < NT; s++) {
        asm volatile("cp.async.wait_group %0;" :: "n"(STAGES - 2));
        __syncthreads();
        int ld = s + STAGES - 1;
        if (ld < NT) {
            int st = (stq + STAGES - 1) % STAGES;
            loadStage(st, ld * KT);
        }
        asm volatile("cp.async.commit_group;");

        int st = stq;
        #pragma unroll
        for (int ks = 0; ks < 2; ks++) {
            int k0 = ks * 16;
            wmma::fragment<wmma::matrix_b, 16, 16, 16, __half, wmma::col_major> bf[2];
            #pragma unroll
            for (int j = 0; j < 2; j++)
                wmma::load_matrix_sync(bf[j], &Bs[st][wn * 32 + j * 16][k0], 40);
            #pragma unroll
            for (int i = 0; i < 4; i++) {
                wmma::fragment<wmma::matrix_a, 16, 16, 16, __half, wmma::row_major> af;
                wmma::load_matrix_sync(af, &As[st][wm * 64 + i * 16][k0], 40);
                #pragma unroll
                for (int j = 0; j < 2; j++)
                    wmma::mma_sync(acc[i][j], af, bf[j], acc[i][j]);
            }
        }
        stq++;
        if (stq == STAGES) stq = 0;
    }

    asm volatile("cp.async.wait_group 0;");
    __syncthreads();

    // two-pass epilogue: pass h stages rows [h*64, h*64+64)
    #pragma unroll
    for (int hp = 0; hp < 2; hp++) {
        if (wm == hp) {
            #pragma unroll
            for (int i = 0; i < 4; i++)
                #pragma unroll
                for (int j = 0; j < 2; j++)
                    wmma::store_matrix_sync(&stage[i * 16][wn * 32 + j * 16],
                                            acc[i][j], 132, wmma::mem_row_major);
        }
        __syncthreads();
        #pragma unroll
        for (int it = 0; it < 8; it++) {
            int idx = tid + it * 256;        // 0..2047 (64 rows x 32 groups)
            int r = idx >> 5;
            int c4 = (idx & 31) * 4;
            int gc = col0 + c4;
            if (gc < NCOLS) {
                int n = row0 + hp * 64 + r;
                float4 v = *(float4*)&stage[r][c4];
                int b = gc / DD;
                int cc = gc - b * DD;
                if (b == 3) {
                    if (n < Nn) *(float4*)&out[(size_t)n * DD + cc] = v;
                } else {
                    __half2 h0 = __floats2half2_rn(v.x, v.y);
                    __half2 h1 = __floats2half2_rn(v.z, v.w);
                    uint2 u = make_uint2(*(uint32_t*)&h0, *(uint32_t*)&h1);
                    if (b == 0) {
                        *(uint2*)&d_Sf[(size_t)n * SFST + cc] = u;
                    } else if (b == 4) {
                        *(uint2*)&d_Sf[(size_t)n * SFST + 304 + cc] = u;
                    } else {
                        int off = (b == 1) ? 0 : (b == 2 ? 320 : 640);
                        *(uint2*)&d_Sh[(size_t)n * SHST + off + cc] = u;
                    }
                }
            }
        }
        __syncthreads();
    }
}

// ---------------- CSR build ----------------
__global__ void zerodeg_kernel(int Nn) {
    int i = blockIdx.x * blockDim.x + threadIdx.x;
    if (i < Nn) d_deg[i] = 0;
}
__global__ void hist_kernel(const int* __restrict__ EI, int Ee) {
    int e = blockIdx.x * blockDim.x + threadIdx.x;
    if (e < Ee) atomicAdd(&d_deg[EI[Ee + e]], 1);
}
__global__ void scan1_kernel(int Nn) {
    __shared__ int sdata[256];
    int t = threadIdx.x;
    int i = blockIdx.x * 256 + t;
    int v = (i < Nn) ? d_deg[i] : 0;
    sdata[t] = v;
    __syncthreads();
    #pragma unroll
    for (int off = 1; off < 256; off <<= 1) {
        int x = (t >= off) ? sdata[t - off] : 0;
        __syncthreads();
        sdata[t] += x;
        __syncthreads();
    }
    if (i < Nn) d_rowptr[i] = sdata[t] - v;
    if (t == 255) d_blksum[blockIdx.x] = sdata[255];
}
__global__ void scan2_kernel(int NB) {
    __shared__ int sdata[256];
    int t = threadIdx.x;
    int v = (t < NB) ? d_blksum[t] : 0;
    sdata[t] = v;
    __syncthreads();
    #pragma unroll
    for (int off = 1; off < 256; off <<= 1) {
        int x = (t >= off) ? sdata[t - off] : 0;
        __syncthreads();
        sdata[t] += x;
        __syncthreads();
    }
    if (t < NB) d_blksum[t] = sdata[t] - v;
}
__global__ void scan3_kernel(int Nn) {
    int i = blockIdx.x * blockDim.x + threadIdx.x;
    if (i >= Nn) return;
    int val = d_rowptr[i] + d_blksum[i >> 8];
    d_rowptr[i] = val;
    d_cursor[i] = val;
    if (i == Nn - 1) d_rowptr[Nn] = val + d_deg[i];
}
__global__ void scatter_kernel(const int* __restrict__ EI, int Ee) {
    int e = blockIdx.x * blockDim.x + threadIdx.x;
    if (e >= Ee) return;
    int dst = EI[Ee + e];
    int pos = atomicAdd(&d_cursor[dst], 1);
    d_edges[pos] = make_int2(EI[e], e);
}

// ---------------- edgeF v5: no max-subtraction ----------------
__global__ void __launch_bounds__(128, 5) edgeF_kernel(const float* __restrict__ EA,
                                                       const float* __restrict__ Wcls,
                                                       const float* __restrict__ bcls,
                                                       float* __restrict__ out, int Nn) {
    __shared__ float sWc[5 * DD];
    __shared__ float sG[8 * DD];
    __shared__ float2 sW2[DD];
    __shared__ float sBcls[5];
    for (int i = threadIdx.x; i < 5 * DD; i += 128) {
        int k = i / DD, c = i - k * DD;
        sWc[i] = Wcls[c * 5 + k];
    }
    for (int i = threadIdx.x; i < 8 * DD; i += 128) sG[i] = d_G8[i];
    for (int i = threadIdx.x; i < DD; i += 128)
        sW2[i] = make_float2(d_W2f[i], d_W2f[DD + i]);
    if (threadIdx.x < 5) sBcls[threadIdx.x] = bcls[threadIdx.x];
    __syncthreads();

    const uint32_t FULL = 0xffffffffu;
    int lane = threadIdx.x & 31;
    int warp = threadIdx.x >> 5;
    int oh = lane >> 3, oj = lane & 7;
    const float sc = 0.115470053837925152f;  // 1/sqrt(75)

    for (int n = blockIdx.x * 4 + warp; n < Nn; n += gridDim.x * 4) {
        int beg = d_rowptr[n], end = d_rowptr[n + 1];
        const __half* rowQ = d_Sf + (size_t)n * SFST;

        float QG = 0.0f;
        {
            const __half* qb = rowQ + oh * 75;
            const float* gb = sG + oj * DD + oh * 75;
            #pragma unroll 5
            for (int c = 0; c < 75; c++)
                QG = fmaf(__half2float(__ldg(&qb[c])), gb[c], QG);
        }

        float2 q2[5], cd2[5], av[5];
        #pragma unroll
        for (int s = 0; s < 5; s++) {
            int col = 2 * lane + 64 * s;
            bool ok = col < DD;
            if (ok) {
                q2[s]  = __half22float2(*(const __half2*)(rowQ + col));
                cd2[s] = __half22float2(*(const __half2*)(rowQ + 304 + col));
            } else {
                q2[s] = make_float2(0, 0);
                cd2[s] = make_float2(0, 0);
            }
            av[s] = make_float2(0, 0);
        }
        float Tacc = 0.0f;

        for (int p = beg; p < end; p++) {
            int2 se = __ldg(&d_edges[p]);
            const __half* rowS = d_Sh + (size_t)se.x * SHST;
            float4 ea = __ldg((const float4*)&EA[4 * se.y]);

            uint32_t kh[5], vh[5], ch[5];
            #pragma unroll
            for (int s = 0; s < 5; s++) {
                int col = 2 * lane + 64 * s;
                bool ok = col < DD;
                kh[s] = ok ? __ldg((const uint32_t*)(rowS + col)) : 0u;
                vh[s] = ok ? __ldg((const uint32_t*)(rowS + 320 + col)) : 0u;
                ch[s] = ok ? __ldg((const uint32_t*)(rowS + 640 + col)) : 0u;
            }

            float vf0[5], vf1[5];
            float l0 = 0, l1 = 0, l2 = 0, l3 = 0, l4 = 0;
            float a0 = 0, a1 = 0, a2 = 0, a3 = 0;
            #pragma unroll
            for (int s = 0; s < 5; s++) {
                int col = 2 * lane + 64 * s;
                float2 kf = __half22float2(*(__half2*)&kh[s]);
                float2 vf = __half22float2(*(__half2*)&vh[s]);
                float2 cf = __half22float2(*(__half2*)&ch[s]);
                vf0[s] = vf.x; vf1[s] = vf.y;
                if (col < DD) {
                    #pragma unroll
                    for (int i = 0; i < 2; i++) {
                        int c = col + i;
                        float2 w2 = sW2[c];
                        float cdv = i ? cd2[s].y : cd2[s].x;
                        float csv = i ? cf.y : cf.x;
                        float h = fast_tanh(cdv + csv + ea.z * w2.x + ea.w * w2.y);
                        l0 = fmaf(h, sWc[c], l0);
                        l1 = fmaf(h, sWc[DD + c], l1);
                        l2 = fmaf(h, sWc[2 * DD + c], l2);
                        l3 = fmaf(h, sWc[3 * DD + c], l3);
                        l4 = fmaf(h, sWc[4 * DD + c], l4);
                        float pr = (i ? q2[s].y : q2[s].x) * (i ? kf.y : kf.x);
                        if (c < 75) a0 += pr;
                        else if (c < 150) a1 += pr;
                        else if (c < 225) a2 += pr;
                        else a3 += pr;
                    }
                }
            }

            #pragma unroll
            for (int o = 16; o; o >>= 1) {
                l0 += __shfl_xor_sync(FULL, l0, o);
                l1 += __shfl_xor_sync(FULL, l1, o);
                l2 += __shfl_xor_sync(FULL, l2, o);
                l3 += __shfl_xor_sync(FULL, l3, o);
                l4 += __shfl_xor_sync(FULL, l4, o);
                a0 += __shfl_xor_sync(FULL, a0, o);
                a1 += __shfl_xor_sync(FULL, a1, o);
                a2 += __shfl_xor_sync(FULL, a2, o);
                a3 += __shfl_xor_sync(FULL, a3, o);
            }
            // softmax without max-subtraction (logits bounded, safe)
            float p0 = __expf(l0 + sBcls[0]), p1 = __expf(l1 + sBcls[1]);
            float p2 = __expf(l2 + sBcls[2]), p3 = __expf(l3 + sBcls[3]);
            float p4 = __expf(l4 + sBcls[4]);
            float inv = __fdividef(1.0f, p0 + p1 + p2 + p3 + p4);
            p0 *= inv; p1 *= inv; p2 *= inv; p3 *= inv; p4 *= inv;
            float t0 = ea.x > 0.0f ? 1.0f : 0.0f;
            float t1 = ea.y < 0.0f ? 1.0f : 0.0f;

            float pj = (oj == 0) ? p0 : (oj == 1) ? p1 : (oj == 2) ? p2 : (oj == 3) ? p3
                      : (oj == 4) ? p4 : (oj == 5) ? t0 : (oj == 6) ? t1 : 1.0f;

            float qef = pj * QG;
            qef += __shfl_xor_sync(FULL, qef, 1, 8);
            qef += __shfl_xor_sync(FULL, qef, 2, 8);
            qef += __shfl_xor_sync(FULL, qef, 4, 8);

            float ah = (oh == 0) ? a0 : (oh == 1) ? a1 : (oh == 2) ? a2 : a3;
            float wv = __expf((ah + qef) * sc);

            float w0 = __shfl_sync(FULL, wv, 0);
            float w1 = __shfl_sync(FULL, wv, 8);
            float w2h = __shfl_sync(FULL, wv, 16);
            float w3h = __shfl_sync(FULL, wv, 24);

            Tacc = fmaf(wv, pj, Tacc);

            #pragma unroll
            for (int s = 0; s < 5; s++) {
                int col = 2 * lane + 64 * s;
                if (col < DD) {
                    float wa = col < 75 ? w0 : (col < 150 ? w1 : (col < 225 ? w2h : w3h));
                    int c1 = col + 1;
                    float wb = c1 < 75 ? w0 : (c1 < 150 ? w1 : (c1 < 225 ? w2h : w3h));
                    av[s].x = fmaf(wa, vf0[s], av[s].x);
                    av[s].y = fmaf(wb, vf1[s], av[s].y);
                }
            }
        }

        #pragma unroll
        for (int s = 0; s < 5; s++) {
            int col = 2 * lane + 64 * s;
            bool ok = col < DD;
            #pragma unroll
            for (int i = 0; i < 2; i++) {
                int cc = ok ? col + i : 0;
                int h = cc < 75 ? 0 : (cc < 150 ? 1 : (cc < 225 ? 2 : 3));
                int base = h * 8;
                float add = i ? av[s].y : av[s].x;
                float den = 0.0f;
                #pragma unroll
                for (int jj = 0; jj < 8; jj++) {
                    float tv = __shfl_sync(FULL, Tacc, base + jj);
                    add = fmaf(tv, sG[jj * DD + cc], add);
                    if (jj == 7) den = tv;
                }
                if (ok) {
                    float invd = den > 0.0f ? __fdividef(1.0f, den) : 0.0f;
                    out[(size_t)n * DD + cc] += add * invd;
                }
            }
        }
    }
}

// ---------------- host launcher ----------------
extern "C" void kernel_launch(void* const* d_in, const int* in_sizes, int n_in,
                              void* d_out, int out_size) {
    const float* x     = (const float*)d_in[0];
    const int*   EI    = (const int*)d_in[1];
    const float* EA    = (const float*)d_in[2];
    const float* nrm   = (const float*)d_in[3];
    const float* Wq    = (const float*)d_in[4];
    const float* bq    = (const float*)d_in[5];
    const float* Wk    = (const float*)d_in[6];
    const float* bk    = (const float*)d_in[7];
    const float* Wv    = (const float*)d_in[8];
    const float* bv    = (const float*)d_in[9];
    const float* We    = (const float*)d_in[10];
    const float* Wn    = (const float*)d_in[11];
    const float* bn    = (const float*)d_in[12];
    const float* Wxy   = (const float*)d_in[13];
    const float* bxy   = (const float*)d_in[14];
    const float* Wloc  = (const float*)d_in[15];
    const float* bloc  = (const float*)d_in[16];
    const float* Wobj  = (const float*)d_in[17];
    const float* bobj  = (const float*)d_in[18];
    const float* Wfus  = (const float*)d_in[19];
    const float* bfus  = (const float*)d_in[20];
    const float* Wcls  = (const float*)d_in[21];
    const float* bcls  = (const float*)d_in[22];
    const float* Wskip = (const float*)d_in[23];
    const float* bskip = (const float*)d_in[24];
    const float* vocab = (const float*)d_in[25];

    int Nn = in_sizes[0] / DD;
    int Ee = in_sizes[1] / 2;
    float* out = (float*)d_out;

    static bool init_done = false;
    static cudaStream_t s2;
    static cudaEvent_t ev0, ev1;
    const int gemm_smem = STAGES * (128 * 40 + 128 * 40) * 2;   // 61440 B
    if (!init_done) {
        cudaFuncSetAttribute(gemm_fp16_kernel, cudaFuncAttributeMaxDynamicSharedMemorySize, gemm_smem);
        cudaStreamCreateWithFlags(&s2, cudaStreamNonBlocking);
        cudaEventCreateWithFlags(&ev0, cudaEventDisableTiming);
        cudaEventCreateWithFlags(&ev1, cudaEventDisableTiming);
        init_done = true;
    }

    cudaEventRecord(ev0, 0);
    cudaStreamWaitEvent(s2, ev0, 0);
    int NB = (Nn + 255) / 256;
    zerodeg_kernel<<<NB, 256, 0, s2>>>(Nn);
    hist_kernel<<<(Ee + 255) / 256, 256, 0, s2>>>(EI, Ee);
    scan1_kernel<<<NB, 256, 0, s2>>>(Nn);
    scan2_kernel<<<1, 256, 0, s2>>>(NB);
    scan3_kernel<<<NB, 256, 0, s2>>>(Nn);
    scatter_kernel<<<(Ee + 255) / 256, 256, 0, s2>>>(EI, Ee);
    cudaEventRecord(ev1, s2);

    fold1b_kernel<<<DD, 128>>>(Wn, Wxy, Wloc, Wfus, vocab, bxy, bn, bobj, bloc, bfus);
    fold2b_kernel<<<DD, 64>>>(We);
    buildA_kernel<<<(Nn * 304 + 255) / 256, 256>>>(x, nrm, Nn);
    buildW_kernel<<<(NCOLS * 304 + 255) / 256, 256>>>(Wq, Wk, Wv, Wskip, Wobj, bq, bk, bv, bskip);

    dim3 gg(15, MPAD / 128);
    gemm_fp16_kernel<<<gg, 256, gemm_smem>>>(out, Nn);

    cudaStreamWaitEvent(0, ev1, 0);
    edgeF_kernel<<<1480, 128>>>(EA, Wcls, bcls, out, Nn);
}

// round 17
// speedup vs baseline: 1.6233x; 1.0892x over previous
#include <cuda_runtime.h>
#include <cuda_fp16.h>
#include <mma.h>
#include <math.h>
#include <stdint.h>

using namespace nvcuda;

#define DD 300
#define NCOLS 1800
#define KK2 320
#define MAXN 50000
#define MAXE 250000
#define MPAD 50048
#define STAGES 4
#define KT 32
#define NT (KK2 / KT)
#define SFST 608            // d_Sf (fp16): Q[0..300), Cd[304..604)
#define SHST 960            // d_Sh (fp16): K[0..300), V[320..620), Cs[640..940)

__device__ __half d_Ah[(size_t)MPAD * KK2];
__device__ __half d_WhT[(size_t)1920 * KK2];
__device__ __half d_Sf[(size_t)MPAD * SFST];
__device__ __half d_Sh[(size_t)MPAD * SHST];
__device__ float  d_NLi[3 * DD];
__device__ float  d_NLj[3 * DD];
__device__ float  d_W2f[2 * DD];
__device__ float  d_c0[DD];
__device__ float  d_T8[8 * DD];
__device__ float  d_G8[8 * DD];
__device__ int  d_deg[MAXN];
__device__ int  d_rowptr[MAXN + 1];
__device__ int  d_cursor[MAXN];
__device__ int  d_blksum[256];
__device__ int2 d_edges[MAXE];

__device__ __forceinline__ float fast_tanh(float x) {
    float r;
    asm("tanh.approx.f32 %0, %1;" : "=f"(r) : "f"(x));
    return r;
}

// ---------------- fold1b ----------------
__global__ void __launch_bounds__(128) fold1b_kernel(
        const float* __restrict__ Wn, const float* __restrict__ Wxy,
        const float* __restrict__ Wloc, const float* __restrict__ Wfus,
        const float* __restrict__ vocab, const float* __restrict__ bxy,
        const float* __restrict__ bn, const float* __restrict__ bobj,
        const float* __restrict__ bloc, const float* __restrict__ bfus) {
    int c = blockIdx.x;
    int t = threadIdx.x;
    float pt[16];
    #pragma unroll
    for (int j = 0; j < 16; j++) pt[j] = 0.0f;

    for (int k = t; k < DD; k += 128) {
        float wl0 = Wloc[k * DD + c];
        float wl1 = Wloc[(DD + k) * DD + c];
        float wl2 = Wloc[(2 * DD + k) * DD + c];
        float wn0 = Wn[k], wn1 = Wn[DD + k], wn2 = Wn[2 * DD + k];
        pt[0] = fmaf(wn0, wl1, pt[0]); pt[1] = fmaf(wn1, wl1, pt[1]); pt[2] = fmaf(wn2, wl1, pt[2]);
        pt[3] = fmaf(wn0, wl2, pt[3]); pt[4] = fmaf(wn1, wl2, pt[4]); pt[5] = fmaf(wn2, wl2, pt[5]);
        pt[6] = fmaf(Wxy[k], wl0, pt[6]); pt[7] = fmaf(Wxy[DD + k], wl0, pt[7]);
        pt[8] = fmaf(bxy[k], wl0, pt[8]);
        pt[8] = fmaf(bn[k], wl1 + wl2, pt[8]);
        float wf0 = Wfus[k * DD + c];
        float wf1 = Wfus[(DD + k) * DD + c];
        pt[9]  = fmaf(vocab[2 * DD + k], wf1, pt[9]);
        pt[10] = fmaf(vocab[3 * DD + k], wf1, pt[10]);
        pt[11] = fmaf(vocab[4 * DD + k], wf1, pt[11]);
        pt[12] = fmaf(vocab[5 * DD + k], wf1, pt[12]);
        pt[13] = fmaf(vocab[6 * DD + k], wf1, pt[13]);
        pt[14] = fmaf(vocab[k], wf0, pt[14]);
        pt[15] = fmaf(vocab[DD + k], wf0, pt[15]);
    }

    __shared__ float sd[16][128];
    #pragma unroll
    for (int j = 0; j < 16; j++) sd[j][t] = pt[j];
    __syncthreads();
    #pragma unroll
    for (int off = 64; off; off >>= 1) {
        if (t < off) {
            #pragma unroll
            for (int j = 0; j < 16; j++) sd[j][t] += sd[j][t + off];
        }
        __syncthreads();
    }
    if (t == 0) {
        d_NLi[0 * DD + c] = sd[0][0]; d_NLi[1 * DD + c] = sd[1][0]; d_NLi[2 * DD + c] = sd[2][0];
        d_NLj[0 * DD + c] = sd[3][0]; d_NLj[1 * DD + c] = sd[4][0]; d_NLj[2 * DD + c] = sd[5][0];
        d_W2f[c] = sd[6][0]; d_W2f[DD + c] = sd[7][0];
        d_c0[c] = sd[8][0] + bobj[c] + bloc[c];
        d_T8[0 * DD + c] = sd[9][0];  d_T8[1 * DD + c] = sd[10][0];
        d_T8[2 * DD + c] = sd[11][0]; d_T8[3 * DD + c] = sd[12][0];
        d_T8[4 * DD + c] = sd[13][0]; d_T8[5 * DD + c] = sd[14][0];
        d_T8[6 * DD + c] = sd[15][0]; d_T8[7 * DD + c] = bfus[c];
    }
}

// ---------------- fold2b ----------------
__global__ void __launch_bounds__(64) fold2b_kernel(const float* __restrict__ We) {
    int c = blockIdx.x;
    int t = threadIdx.x;
    float g[8];
    #pragma unroll
    for (int j = 0; j < 8; j++) g[j] = 0.0f;
    for (int k = t; k < DD; k += 64) {
        float w = We[k * DD + c];
        #pragma unroll
        for (int j = 0; j < 8; j++) g[j] = fmaf(d_T8[j * DD + k], w, g[j]);
    }
    __shared__ float sd[8][64];
    #pragma unroll
    for (int j = 0; j < 8; j++) sd[j][t] = g[j];
    __syncthreads();
    #pragma unroll
    for (int off = 32; off; off >>= 1) {
        if (t < off) {
            #pragma unroll
            for (int j = 0; j < 8; j++) sd[j][t] += sd[j][t + off];
        }
        __syncthreads();
    }
    if (t == 0) {
        #pragma unroll
        for (int j = 0; j < 8; j++) d_G8[j * DD + c] = sd[j][0];
    }
}

// ---------------- build A ----------------
__global__ void buildA_kernel(const float* __restrict__ x, const float* __restrict__ nrm, int Nn) {
    int idx = blockIdx.x * blockDim.x + threadIdx.x;
    if (idx >= Nn * 304) return;
    int n = idx / 304, k = idx - n * 304;
    float v;
    if (k < DD) v = x[n * DD + k];
    else if (k < DD + 3) v = nrm[n * 3 + (k - DD)];
    else v = 1.0f;
    d_Ah[(size_t)n * KK2 + k] = __float2half_rn(v);
}

// ---------------- build WhT ----------------
__global__ void buildW_kernel(const float* __restrict__ Wq, const float* __restrict__ Wk,
                              const float* __restrict__ Wv, const float* __restrict__ Wskip,
                              const float* __restrict__ Wobj, const float* __restrict__ bq,
                              const float* __restrict__ bk, const float* __restrict__ bv,
                              const float* __restrict__ bskip) {
    int idx = blockIdx.x * blockDim.x + threadIdx.x;
    if (idx >= NCOLS * 304) return;
    int c = idx / 304, k = idx - c * 304;
    int b = c / DD, cc = c - b * DD;
    float v = 0.0f;
    if (k < DD) {
        if (b == 0) v = Wq[k * DD + cc];
        else if (b == 1) v = Wk[k * DD + cc];
        else if (b == 2) v = Wv[k * DD + cc];
        else if (b == 3) v = Wskip[k * DD + cc];
        else if (b == 4) v = Wobj[k * DD + cc] - Wobj[(DD + k) * DD + cc];
        else v = Wobj[(DD + k) * DD + cc];
    } else if (k < DD + 3) {
        int r = k - DD;
        if (b == 4) v = d_NLi[r * DD + cc];
        else if (b == 5) v = d_NLj[r * DD + cc];
    } else {
        if (b == 0) v = bq[cc];
        else if (b == 1) v = bk[cc];
        else if (b == 2) v = bv[cc];
        else if (b == 3) v = bskip[cc];
        else if (b == 4) v = d_c0[cc];
    }
    d_WhT[(size_t)c * KK2 + k] = __float2half_rn(v);
}

// ---------------- node GEMM: R13 config (4-stage, 2 CTAs/SM, single-pass epilogue) ----
__global__ void __launch_bounds__(256, 2) gemm_fp16_kernel(float* __restrict__ out, int Nn) {
    extern __shared__ __half sm[];
    __half (*As)[128][40] = (__half (*)[128][40])sm;
    __half (*Bs)[128][40] = (__half (*)[128][40])(sm + STAGES * 128 * 40);
    float (*stage)[132] = (float (*)[132])sm;

    int tid = threadIdx.x;
    int wid = tid >> 5;
    int wm = wid >> 2;
    int wn = wid & 3;
    int row0 = blockIdx.y * 128, col0 = blockIdx.x * 128;

    wmma::fragment<wmma::accumulator, 16, 16, 16, float> acc[4][2];
    #pragma unroll
    for (int i = 0; i < 4; i++)
        #pragma unroll
        for (int j = 0; j < 2; j++) wmma::fill_fragment(acc[i][j], 0.0f);

    auto loadStage = [&](int st, int kt) {
        #pragma unroll
        for (int u = 0; u < 2; u++) {
            int idx = tid + 256 * u;
            int row = idx >> 2, seg = idx & 3;
            const __half* ga = &d_Ah[(size_t)(row0 + row) * KK2 + kt + seg * 8];
            uint32_t da = (uint32_t)__cvta_generic_to_shared(&As[st][row][seg * 8]);
            asm volatile("cp.async.cg.shared.global [%0], [%1], 16;" :: "r"(da), "l"(ga));
            const __half* gb = &d_WhT[(size_t)(col0 + row) * KK2 + kt + seg * 8];
            uint32_t db = (uint32_t)__cvta_generic_to_shared(&Bs[st][row][seg * 8]);
            asm volatile("cp.async.cg.shared.global [%0], [%1], 16;" :: "r"(db), "l"(gb));
        }
    };

    #pragma unroll
    for (int i = 0; i < STAGES - 1; i++) {
        loadStage(i, i * KT);
        asm volatile("cp.async.commit_group;");
    }

    for (int s = 0; s < NT; s++) {
        asm volatile("cp.async.wait_group %0;" :: "n"(STAGES - 2));
        __syncthreads();
        int ld = s + STAGES - 1;
        if (ld < NT) loadStage(ld & (STAGES - 1), ld * KT);
        asm volatile("cp.async.commit_group;");

        int st = s & (STAGES - 1);
        #pragma unroll
        for (int ks = 0; ks < 2; ks++) {
            int k0 = ks * 16;
            wmma::fragment<wmma::matrix_b, 16, 16, 16, __half, wmma::col_major> bf[2];
            #pragma unroll
            for (int j = 0; j < 2; j++)
                wmma::load_matrix_sync(bf[j], &Bs[st][wn * 32 + j * 16][k0], 40);
            #pragma unroll
            for (int i = 0; i < 4; i++) {
                wmma::fragment<wmma::matrix_a, 16, 16, 16, __half, wmma::row_major> af;
                wmma::load_matrix_sync(af, &As[st][wm * 64 + i * 16][k0], 40);
                #pragma unroll
                for (int j = 0; j < 2; j++)
                    wmma::mma_sync(acc[i][j], af, bf[j], acc[i][j]);
            }
        }
    }

    asm volatile("cp.async.wait_group 0;");
    __syncthreads();
    #pragma unroll
    for (int i = 0; i < 4; i++)
        #pragma unroll
        for (int j = 0; j < 2; j++)
            wmma::store_matrix_sync(&stage[wm * 64 + i * 16][wn * 32 + j * 16],
                                    acc[i][j], 132, wmma::mem_row_major);
    __syncthreads();

    #pragma unroll
    for (int it = 0; it < 16; it++) {
        int idx = tid + it * 256;
        int r = idx >> 5;
        int c4 = (idx & 31) * 4;
        int gc = col0 + c4;
        if (gc >= NCOLS) continue;
        int n = row0 + r;
        float4 v = *(float4*)&stage[r][c4];
        int b = gc / DD;
        int cc = gc - b * DD;
        if (b == 3) {
            if (n < Nn) *(float4*)&out[(size_t)n * DD + cc] = v;
        } else {
            __half2 h0 = __floats2half2_rn(v.x, v.y);
            __half2 h1 = __floats2half2_rn(v.z, v.w);
            uint2 u = make_uint2(*(uint32_t*)&h0, *(uint32_t*)&h1);
            if (b == 0) {
                *(uint2*)&d_Sf[(size_t)n * SFST + cc] = u;
            } else if (b == 4) {
                *(uint2*)&d_Sf[(size_t)n * SFST + 304 + cc] = u;
            } else {
                int off = (b == 1) ? 0 : (b == 2 ? 320 : 640);
                *(uint2*)&d_Sh[(size_t)n * SHST + off + cc] = u;
            }
        }
    }
}

// ---------------- CSR build ----------------
__global__ void zerodeg_kernel(int Nn) {
    int i = blockIdx.x * blockDim.x + threadIdx.x;
    if (i < Nn) d_deg[i] = 0;
}
__global__ void hist_kernel(const int* __restrict__ EI, int Ee) {
    int e = blockIdx.x * blockDim.x + threadIdx.x;
    if (e < Ee) atomicAdd(&d_deg[EI[Ee + e]], 1);
}
__global__ void scan1_kernel(int Nn) {
    __shared__ int sdata[256];
    int t = threadIdx.x;
    int i = blockIdx.x * 256 + t;
    int v = (i < Nn) ? d_deg[i] : 0;
    sdata[t] = v;
    __syncthreads();
    #pragma unroll
    for (int off = 1; off < 256; off <<= 1) {
        int x = (t >= off) ? sdata[t - off] : 0;
        __syncthreads();
        sdata[t] += x;
        __syncthreads();
    }
    if (i < Nn) d_rowptr[i] = sdata[t] - v;
    if (t == 255) d_blksum[blockIdx.x] = sdata[255];
}
__global__ void scan2_kernel(int NB) {
    __shared__ int sdata[256];
    int t = threadIdx.x;
    int v = (t < NB) ? d_blksum[t] : 0;
    sdata[t] = v;
    __syncthreads();
    #pragma unroll
    for (int off = 1; off < 256; off <<= 1) {
        int x = (t >= off) ? sdata[t - off] : 0;
        __syncthreads();
        sdata[t] += x;
        __syncthreads();
    }
    if (t < NB) d_blksum[t] = sdata[t] - v;
}
__global__ void scan3_kernel(int Nn) {
    int i = blockIdx.x * blockDim.x + threadIdx.x;
    if (i >= Nn) return;
    int val = d_rowptr[i] + d_blksum[i >> 8];
    d_rowptr[i] = val;
    d_cursor[i] = val;
    if (i == Nn - 1) d_rowptr[Nn] = val + d_deg[i];
}
__global__ void scatter_kernel(const int* __restrict__ EI, int Ee) {
    int e = blockIdx.x * blockDim.x + threadIdx.x;
    if (e >= Ee) return;
    int dst = EI[Ee + e];
    int pos = atomicAdd(&d_cursor[dst], 1);
    d_edges[pos] = make_int2(EI[e], e);
}

// ---------------- edgeF v5b: no-max softmax + (se, ea) prefetch ----------------
__global__ void __launch_bounds__(128, 5) edgeF_kernel(const float* __restrict__ EA,
                                                       const float* __restrict__ Wcls,
                                                       const float* __restrict__ bcls,
                                                       float* __restrict__ out, int Nn) {
    __shared__ float sWc[5 * DD];
    __shared__ float sG[8 * DD];
    __shared__ float2 sW2[DD];
    __shared__ float sBcls[5];
    for (int i = threadIdx.x; i < 5 * DD; i += 128) {
        int k = i / DD, c = i - k * DD;
        sWc[i] = Wcls[c * 5 + k];
    }
    for (int i = threadIdx.x; i < 8 * DD; i += 128) sG[i] = d_G8[i];
    for (int i = threadIdx.x; i < DD; i += 128)
        sW2[i] = make_float2(d_W2f[i], d_W2f[DD + i]);
    if (threadIdx.x < 5) sBcls[threadIdx.x] = bcls[threadIdx.x];
    __syncthreads();

    const uint32_t FULL = 0xffffffffu;
    int lane = threadIdx.x & 31;
    int warp = threadIdx.x >> 5;
    int oh = lane >> 3, oj = lane & 7;
    const float sc = 0.115470053837925152f;  // 1/sqrt(75)

    for (int n = blockIdx.x * 4 + warp; n < Nn; n += gridDim.x * 4) {
        int beg = d_rowptr[n], end = d_rowptr[n + 1];
        const __half* rowQ = d_Sf + (size_t)n * SFST;

        float QG = 0.0f;
        {
            const __half* qb = rowQ + oh * 75;
            const float* gb = sG + oj * DD + oh * 75;
            #pragma unroll 5
            for (int c = 0; c < 75; c++)
                QG = fmaf(__half2float(__ldg(&qb[c])), gb[c], QG);
        }

        float2 q2[5], cd2[5], av[5];
        #pragma unroll
        for (int s = 0; s < 5; s++) {
            int col = 2 * lane + 64 * s;
            bool ok = col < DD;
            if (ok) {
                q2[s]  = __half22float2(*(const __half2*)(rowQ + col));
                cd2[s] = __half22float2(*(const __half2*)(rowQ + 304 + col));
            } else {
                q2[s] = make_float2(0, 0);
                cd2[s] = make_float2(0, 0);
            }
            av[s] = make_float2(0, 0);
        }
        float Tacc = 0.0f;

        // prefetch (se, ea) for the first edge
        int2 se_n = make_int2(0, 0);
        float4 ea_n = make_float4(0, 0, 0, 0);
        if (beg < end) {
            se_n = __ldg(&d_edges[beg]);
            ea_n = __ldg((const float4*)&EA[4 * se_n.y]);
        }

        for (int p = beg; p < end; p++) {
            int2 se = se_n;
            float4 ea = ea_n;
            if (p + 1 < end) {
                se_n = __ldg(&d_edges[p + 1]);
                ea_n = __ldg((const float4*)&EA[4 * se_n.y]);
            }
            const __half* rowS = d_Sh + (size_t)se.x * SHST;

            uint32_t kh[5], vh[5], ch[5];
            #pragma unroll
            for (int s = 0; s < 5; s++) {
                int col = 2 * lane + 64 * s;
                bool ok = col < DD;
                kh[s] = ok ? __ldg((const uint32_t*)(rowS + col)) : 0u;
                vh[s] = ok ? __ldg((const uint32_t*)(rowS + 320 + col)) : 0u;
                ch[s] = ok ? __ldg((const uint32_t*)(rowS + 640 + col)) : 0u;
            }

            float vf0[5], vf1[5];
            float l0 = 0, l1 = 0, l2 = 0, l3 = 0, l4 = 0;
            float a0 = 0, a1 = 0, a2 = 0, a3 = 0;
            #pragma unroll
            for (int s = 0; s < 5; s++) {
                int col = 2 * lane + 64 * s;
                float2 kf = __half22float2(*(__half2*)&kh[s]);
                float2 vf = __half22float2(*(__half2*)&vh[s]);
                float2 cf = __half22float2(*(__half2*)&ch[s]);
                vf0[s] = vf.x; vf1[s] = vf.y;
                if (col < DD) {
                    #pragma unroll
                    for (int i = 0; i < 2; i++) {
                        int c = col + i;
                        float2 w2 = sW2[c];
                        float cdv = i ? cd2[s].y : cd2[s].x;
                        float csv = i ? cf.y : cf.x;
                        float h = fast_tanh(cdv + csv + ea.z * w2.x + ea.w * w2.y);
                        l0 = fmaf(h, sWc[c], l0);
                        l1 = fmaf(h, sWc[DD + c], l1);
                        l2 = fmaf(h, sWc[2 * DD + c], l2);
                        l3 = fmaf(h, sWc[3 * DD + c], l3);
                        l4 = fmaf(h, sWc[4 * DD + c], l4);
                        float pr = (i ? q2[s].y : q2[s].x) * (i ? kf.y : kf.x);
                        if (c < 75) a0 += pr;
                        else if (c < 150) a1 += pr;
                        else if (c < 225) a2 += pr;
                        else a3 += pr;
                    }
                }
            }

            #pragma unroll
            for (int o = 16; o; o >>= 1) {
                l0 += __shfl_xor_sync(FULL, l0, o);
                l1 += __shfl_xor_sync(FULL, l1, o);
                l2 += __shfl_xor_sync(FULL, l2, o);
                l3 += __shfl_xor_sync(FULL, l3, o);
                l4 += __shfl_xor_sync(FULL, l4, o);
                a0 += __shfl_xor_sync(FULL, a0, o);
                a1 += __shfl_xor_sync(FULL, a1, o);
                a2 += __shfl_xor_sync(FULL, a2, o);
                a3 += __shfl_xor_sync(FULL, a3, o);
            }
            // no-max softmax (logits bounded)
            float p0 = __expf(l0 + sBcls[0]), p1 = __expf(l1 + sBcls[1]);
            float p2 = __expf(l2 + sBcls[2]), p3 = __expf(l3 + sBcls[3]);
            float p4 = __expf(l4 + sBcls[4]);
            float inv = __fdividef(1.0f, p0 + p1 + p2 + p3 + p4);
            p0 *= inv; p1 *= inv; p2 *= inv; p3 *= inv; p4 *= inv;
            float t0 = ea.x > 0.0f ? 1.0f : 0.0f;
            float t1 = ea.y < 0.0f ? 1.0f : 0.0f;

            float pj = (oj == 0) ? p0 : (oj == 1) ? p1 : (oj == 2) ? p2 : (oj == 3) ? p3
                      : (oj == 4) ? p4 : (oj == 5) ? t0 : (oj == 6) ? t1 : 1.0f;

            float qef = pj * QG;
            qef += __shfl_xor_sync(FULL, qef, 1, 8);
            qef += __shfl_xor_sync(FULL, qef, 2, 8);
            qef += __shfl_xor_sync(FULL, qef, 4, 8);

            float ah = (oh == 0) ? a0 : (oh == 1) ? a1 : (oh == 2) ? a2 : a3;
            float wv = __expf((ah + qef) * sc);

            float w0 = __shfl_sync(FULL, wv, 0);
            float w1 = __shfl_sync(FULL, wv, 8);
            float w2h = __shfl_sync(FULL, wv, 16);
            float w3h = __shfl_sync(FULL, wv, 24);

            Tacc = fmaf(wv, pj, Tacc);

            #pragma unroll
            for (int s = 0; s < 5; s++) {
                int col = 2 * lane + 64 * s;
                if (col < DD) {
                    float wa = col < 75 ? w0 : (col < 150 ? w1 : (col < 225 ? w2h : w3h));
                    int c1 = col + 1;
                    float wb = c1 < 75 ? w0 : (c1 < 150 ? w1 : (c1 < 225 ? w2h : w3h));
                    av[s].x = fmaf(wa, vf0[s], av[s].x);
                    av[s].y = fmaf(wb, vf1[s], av[s].y);
                }
            }
        }

        #pragma unroll
        for (int s = 0; s < 5; s++) {
            int col = 2 * lane + 64 * s;
            bool ok = col < DD;
            #pragma unroll
            for (int i = 0; i < 2; i++) {
                int cc = ok ? col + i : 0;
                int h = cc < 75 ? 0 : (cc < 150 ? 1 : (cc < 225 ? 2 : 3));
                int base = h * 8;
                float add = i ? av[s].y : av[s].x;
                float den = 0.0f;
                #pragma unroll
                for (int jj = 0; jj < 8; jj++) {
                    float tv = __shfl_sync(FULL, Tacc, base + jj);
                    add = fmaf(tv, sG[jj * DD + cc], add);
                    if (jj == 7) den = tv;
                }
                if (ok) {
                    float invd = den > 0.0f ? __fdividef(1.0f, den) : 0.0f;
                    out[(size_t)n * DD + cc] += add * invd;
                }
            }
        }
    }
}

// ---------------- host launcher ----------------
extern "C" void kernel_launch(void* const* d_in, const int* in_sizes, int n_in,
                              void* d_out, int out_size) {
    const float* x     = (const float*)d_in[0];
    const int*   EI    = (const int*)d_in[1];
    const float* EA    = (const float*)d_in[2];
    const float* nrm   = (const float*)d_in[3];
    const float* Wq    = (const float*)d_in[4];
    const float* bq    = (const float*)d_in[5];
    const float* Wk    = (const float*)d_in[6];
    const float* bk    = (const float*)d_in[7];
    const float* Wv    = (const float*)d_in[8];
    const float* bv    = (const float*)d_in[9];
    const float* We    = (const float*)d_in[10];
    const float* Wn    = (const float*)d_in[11];
    const float* bn    = (const float*)d_in[12];
    const float* Wxy   = (const float*)d_in[13];
    const float* bxy   = (const float*)d_in[14];
    const float* Wloc  = (const float*)d_in[15];
    const float* bloc  = (const float*)d_in[16];
    const float* Wobj  = (const float*)d_in[17];
    const float* bobj  = (const float*)d_in[18];
    const float* Wfus  = (const float*)d_in[19];
    const float* bfus  = (const float*)d_in[20];
    const float* Wcls  = (const float*)d_in[21];
    const float* bcls  = (const float*)d_in[22];
    const float* Wskip = (const float*)d_in[23];
    const float* bskip = (const float*)d_in[24];
    const float* vocab = (const float*)d_in[25];

    int Nn = in_sizes[0] / DD;
    int Ee = in_sizes[1] / 2;
    float* out = (float*)d_out;

    static bool init_done = false;
    static cudaStream_t s2;
    static cudaEvent_t ev0, ev1, ev2;
    const int gemm_smem = STAGES * (128 * 40 + 128 * 40) * 2;   // 81920 B
    if (!init_done) {
        cudaFuncSetAttribute(gemm_fp16_kernel, cudaFuncAttributeMaxDynamicSharedMemorySize, gemm_smem);
        cudaStreamCreateWithFlags(&s2, cudaStreamNonBlocking);
        cudaEventCreateWithFlags(&ev0, cudaEventDisableTiming);
        cudaEventCreateWithFlags(&ev1, cudaEventDisableTiming);
        cudaEventCreateWithFlags(&ev2, cudaEventDisableTiming);
        init_done = true;
    }

    // side stream: buildA first (needed by GEMM), then CSR chain (needed by edgeF)
    cudaEventRecord(ev0, 0);
    cudaStreamWaitEvent(s2, ev0, 0);
    buildA_kernel<<<(Nn * 304 + 255) / 256, 256, 0, s2>>>(x, nrm, Nn);
    cudaEventRecord(ev2, s2);
    int NB = (Nn + 255) / 256;
    zerodeg_kernel<<<NB, 256, 0, s2>>>(Nn);
    hist_kernel<<<(Ee + 255) / 256, 256, 0, s2>>>(EI, Ee);
    scan1_kernel<<<NB, 256, 0, s2>>>(Nn);
    scan2_kernel<<<1, 256, 0, s2>>>(NB);
    scan3_kernel<<<NB, 256, 0, s2>>>(Nn);
    scatter_kernel<<<(Ee + 255) / 256, 256, 0, s2>>>(EI, Ee);
    cudaEventRecord(ev1, s2);

    // main chain
    fold1b_kernel<<<DD, 128>>>(Wn, Wxy, Wloc, Wfus, vocab, bxy, bn, bobj, bloc, bfus);
    fold2b_kernel<<<DD, 64>>>(We);
    buildW_kernel<<<(NCOLS * 304 + 255) / 256, 256>>>(Wq, Wk, Wv, Wskip, Wobj, bq, bk, bv, bskip);

    cudaStreamWaitEvent(0, ev2, 0);    // A ready
    dim3 gg(15, MPAD / 128);
    gemm_fp16_kernel<<<gg, 256, gemm_smem>>>(out, Nn);

    cudaStreamWaitEvent(0, ev1, 0);    // CSR ready
    edgeF_kernel<<<1480, 128>>>(EA, Wcls, bcls, out, Nn);
}